// round 9
// baseline (speedup 1.0000x reference)
#include <cuda_runtime.h>
#include <cuda_fp16.h>
#include <cstdint>

#define NN 100000
#define FDIM 128
#define EMAX 1700032
#define NBMAX 512

typedef unsigned long long ull;

// Scratch (device globals — allocation-free per harness rules)
__device__ __half g_h16[NN * FDIM];   // fp16 transformed features (messages)
__device__ float g_out[NN * FDIM];    // aggregated + relu(·+bias) output (fp32)
__device__ float g_asrc[NN * 4];
__device__ float g_adst[NN * 4];
__device__ float g_wpad[FDIM * 64];   // Wc zero-padded to 128x64
__device__ float g_w1tf[FDIM * FDIM]; // W1 pre-rounded to tf32 (rna)
__device__ float g_w2tf[FDIM * FDIM]; // W2 pre-rounded to tf32 (rna)
__device__ int   g_rowptr[NN + 1];
__device__ int   g_wcur[NN];
__device__ int   g_csrc[EMAX];
__device__ int   g_bsum[NBMAX];

// ---------------------------------------------------------------------------
// packed f32x2 helpers (classifier GEMM)
// ---------------------------------------------------------------------------
#define PACK2(out, lo, hi) \
    asm("mov.b64 %0, {%1, %2};" : "=l"(out) : "f"(lo), "f"(hi))
#define UNPK2(lo, hi, in) \
    asm("mov.b64 {%0, %1}, %2;" : "=f"(lo), "=f"(hi) : "l"(in))
#define FMA2(d, a, b, c) \
    asm("fma.rn.f32x2 %0, %1, %2, %3;" : "=l"(d) : "l"(a), "l"(b), "l"(c))

__device__ __forceinline__ uint32_t f2tf(float f) {
    uint32_t r;
    asm("cvt.rna.tf32.f32 %0, %1;" : "=r"(r) : "f"(f));
    return r;
}
#define MMA_TF32(c, a, b) \
    asm volatile("mma.sync.aligned.m16n8k8.row.col.f32.tf32.tf32.f32 " \
        "{%0,%1,%2,%3}, {%4,%5,%6,%7}, {%8,%9}, {%0,%1,%2,%3};" \
        : "+f"((c)[0]), "+f"((c)[1]), "+f"((c)[2]), "+f"((c)[3]) \
        : "r"((a)[0]), "r"((a)[1]), "r"((a)[2]), "r"((a)[3]), \
          "r"((b)[0]), "r"((b)[1]))

__device__ __forceinline__ uint32_t s2u(const void* p) {
    uint32_t a;
    asm("{ .reg .u64 t; cvta.to.shared.u64 t, %1; cvt.u32.u64 %0, t; }"
        : "=r"(a) : "l"(p));
    return a;
}
__device__ __forceinline__ void cpa16(uint32_t dst, const void* src, bool pred) {
    int sz = pred ? 16 : 0;   // src-size 0 -> zero-fill, no read
    asm volatile("cp.async.ca.shared.global [%0], [%1], 16, %2;"
                 :: "r"(dst), "l"(src), "r"(sz));
}
#define CPA_COMMIT() asm volatile("cp.async.commit_group;" ::: "memory")
#define CPA_WAIT(n)  asm volatile("cp.async.wait_group %0;" :: "n"(n) : "memory")

// dynamic smem layout (floats): A double-buf, W double-buf, att vectors
#define OFF_A0   0
#define OFF_A1   4608        // 128*36
#define OFF_W0   9216
#define OFF_W1   13440       // + 32*132
#define OFF_ATTS 17664
#define OFF_ATTD 17792
#define SMEM_FLOATS 17920    // 71680 bytes

// ---------------------------------------------------------------------------
// TF32 tensor GEMM, cp.async double-buffered, fused attention epilogue:
//   h16[M,128] = A[M,128] @ Wtf[128,128]    (A raw fp32 -> tf32 truncation)
//   a_s/a_d from fp32 accumulators.
// BM=128, BN=128, BK=32, 256 threads (8 warps: 4M x 2N).
// ---------------------------------------------------------------------------
__global__ void __launch_bounds__(256) mma_gemm_k(
    const float* __restrict__ A, const float* __restrict__ Wtf,
    __half* __restrict__ h16,
    float* __restrict__ a_s, float* __restrict__ a_d,
    const float* __restrict__ att_s, const float* __restrict__ att_d, int M)
{
    extern __shared__ float smem[];
    const uint32_t sb = s2u(smem);
    const int tid = threadIdx.x;
    const int lane = tid & 31;
    const int w = tid >> 5;
    const int wm = (w & 3) * 32;
    const int wn = (w >> 2) * 64;
    const int r0 = blockIdx.x * 128;

    if (tid < 128) {
        smem[OFF_ATTS + tid] = att_s[tid];
        smem[OFF_ATTD + tid] = att_d[tid];
    }

    // ---- tile loaders (cp.async) ----
    const int arow = tid >> 1;                 // 0..127 (2 thr/row, 2 cg each)
    const int acg0 = (tid & 1) * 4;            // cg 0..7 covered by i-loop
    const int wk = tid >> 3;                   // 0..31
    const int wng = (tid & 7) * 4;             // 4 float4 per row via i-loop

    auto load_slab = [&](int kb, int buf) {
        const uint32_t aB = sb + (buf ? OFF_A1 : OFF_A0) * 4;
        const uint32_t wB = sb + (buf ? OFF_W1 : OFF_W0) * 4;
        int gr = r0 + arow;
        bool v = gr < M;
        const float* asrc = A + (size_t)(v ? gr : 0) * 128 + kb * 32;
#pragma unroll
        for (int i = 0; i < 2; i++) {
            int cg = acg0 + i * 8;             // cg in {0..7}*4: acg0, acg0+8? no:
            // acg0 in {0,4}; i*8 -> {0,8} wrong; recompute below
        }
        // A: 128 rows x 8 float4; 256 threads -> 4 per thread
#pragma unroll
        for (int i = 0; i < 4; i++) {
            int idx = tid + i * 256;
            int row = idx >> 3, cg = idx & 7;
            int g = r0 + row;
            bool ok = g < M;
            cpa16(aB + (row * 36 + cg * 4) * 4,
                  A + (size_t)(ok ? g : 0) * 128 + kb * 32 + cg * 4, ok);
        }
        // W: 32 rows x 32 float4; 4 per thread
#pragma unroll
        for (int i = 0; i < 4; i++) {
            int idx = tid + i * 256;
            int k = idx >> 5, ng = idx & 31;
            cpa16(wB + (k * 132 + ng * 4) * 4,
                  Wtf + (size_t)(kb * 32 + k) * 128 + ng * 4, true);
        }
        (void)asrc; (void)v; (void)wk; (void)wng;
    };

    float acc[2][8][4];
#pragma unroll
    for (int tm = 0; tm < 2; tm++)
#pragma unroll
        for (int tn = 0; tn < 8; tn++)
#pragma unroll
            for (int i = 0; i < 4; i++) acc[tm][tn][i] = 0.f;

    load_slab(0, 0);
    CPA_COMMIT();

#pragma unroll
    for (int kb = 0; kb < 4; kb++) {
        const int buf = kb & 1;
        if (kb < 3) {
            load_slab(kb + 1, buf ^ 1);
            CPA_COMMIT();
            CPA_WAIT(1);
        } else {
            CPA_WAIT(0);
        }
        __syncthreads();

        const float* sA = smem + (buf ? OFF_A1 : OFF_A0);
        const float* sW = smem + (buf ? OFF_W1 : OFF_W0);

#pragma unroll
        for (int k8 = 0; k8 < 4; k8++) {
            const int kq = k8 * 8 + (lane & 3);
            const int rb = wm + (lane >> 2);
            const int nb = wn + (lane >> 2);
            uint32_t a[2][4], b[8][2];
#pragma unroll
            for (int tm = 0; tm < 2; tm++) {
                a[tm][0] = __float_as_uint(sA[(rb + tm * 16 + 0) * 36 + kq]);
                a[tm][1] = __float_as_uint(sA[(rb + tm * 16 + 8) * 36 + kq]);
                a[tm][2] = __float_as_uint(sA[(rb + tm * 16 + 0) * 36 + kq + 4]);
                a[tm][3] = __float_as_uint(sA[(rb + tm * 16 + 8) * 36 + kq + 4]);
            }
#pragma unroll
            for (int tn = 0; tn < 8; tn++) {
                b[tn][0] = __float_as_uint(sW[(kq + 0) * 132 + nb + tn * 8]);
                b[tn][1] = __float_as_uint(sW[(kq + 4) * 132 + nb + tn * 8]);
            }
#pragma unroll
            for (int tm = 0; tm < 2; tm++)
#pragma unroll
                for (int tn = 0; tn < 8; tn++)
                    MMA_TF32(acc[tm][tn], a[tm], b[tn]);
        }
        __syncthreads();
    }

    // ---- fused epilogue: fp16 store + attn logits from fp32 accs ----
    const float* satt_s = smem + OFF_ATTS;
    const float* satt_d = smem + OFF_ATTD;
    const int headA = wn >> 5;
#pragma unroll
    for (int tm = 0; tm < 2; tm++)
#pragma unroll
        for (int h2 = 0; h2 < 2; h2++) {
            int gr = r0 + wm + tm * 16 + (lane >> 2) + 8 * h2;
            if (gr < M) {
#pragma unroll
                for (int tn = 0; tn < 8; tn++) {
                    __half2 hh = __floats2half2_rn(acc[tm][tn][2 * h2],
                                                   acc[tm][tn][2 * h2 + 1]);
                    *(uint32_t*)(h16 + (size_t)gr * 128 + wn + tn * 8 +
                                 (lane & 3) * 2) = *(uint32_t*)&hh;
                }
            }
            float s0 = 0.f, d0 = 0.f, s1 = 0.f, d1 = 0.f;
#pragma unroll
            for (int tn = 0; tn < 4; tn++) {
                int col = wn + tn * 8 + (lane & 3) * 2;
                float x0 = acc[tm][tn][2 * h2], x1 = acc[tm][tn][2 * h2 + 1];
                s0 += x0 * satt_s[col] + x1 * satt_s[col + 1];
                d0 += x0 * satt_d[col] + x1 * satt_d[col + 1];
            }
#pragma unroll
            for (int tn = 4; tn < 8; tn++) {
                int col = wn + tn * 8 + (lane & 3) * 2;
                float x0 = acc[tm][tn][2 * h2], x1 = acc[tm][tn][2 * h2 + 1];
                s1 += x0 * satt_s[col] + x1 * satt_s[col + 1];
                d1 += x0 * satt_d[col] + x1 * satt_d[col + 1];
            }
#pragma unroll
            for (int off = 1; off <= 2; off <<= 1) {
                s0 += __shfl_xor_sync(0xFFFFFFFF, s0, off);
                d0 += __shfl_xor_sync(0xFFFFFFFF, d0, off);
                s1 += __shfl_xor_sync(0xFFFFFFFF, s1, off);
                d1 += __shfl_xor_sync(0xFFFFFFFF, d1, off);
            }
            if ((lane & 3) == 0 && gr < M) {
                a_s[(size_t)gr * 4 + headA] = s0;
                a_d[(size_t)gr * 4 + headA] = d0;
                a_s[(size_t)gr * 4 + headA + 1] = s1;
                a_d[(size_t)gr * 4 + headA + 1] = d1;
            }
        }
}

// ---------------------------------------------------------------------------
// Classifier GEMM (exact fp32 FFMA2): C[M,40] = A @ Wpad[128,64] + b_out
// (A already has relu+bias applied by agg)
// ---------------------------------------------------------------------------
__global__ void __launch_bounds__(256) gemm_cls_k(
    const float* __restrict__ A, const float* __restrict__ W,
    float* __restrict__ C, const float* __restrict__ bias_out, int M)
{
    __shared__ float sAT[32][130];
    __shared__ float sW[32][64];

    const int tid = threadIdx.x;
    const int tx = tid & 15;
    const int ty = tid >> 4;
    const int r0 = blockIdx.x * 128;

    ull acc[4][4];
#pragma unroll
    for (int p = 0; p < 4; p++)
#pragma unroll
        for (int c = 0; c < 4; c++) acc[p][c] = 0ull;

    for (int k0 = 0; k0 < 128; k0 += 32) {
#pragma unroll
        for (int i = 0; i < 4; i++) {
            int f = tid + i * 256;
            int row = f >> 3;
            int cg = f & 7;
            int grow = r0 + row;
            float4 v = make_float4(0.f, 0.f, 0.f, 0.f);
            if (grow < M)
                v = *(const float4*)(A + (size_t)grow * 128 + k0 + cg * 4);
            sAT[cg * 4 + 0][row] = v.x;
            sAT[cg * 4 + 1][row] = v.y;
            sAT[cg * 4 + 2][row] = v.z;
            sAT[cg * 4 + 3][row] = v.w;
        }
#pragma unroll
        for (int i = 0; i < 2; i++) {
            int f = tid + i * 256;
            int row = f >> 4;
            int cg = f & 15;
            *(float4*)&sW[row][cg * 4] =
                *(const float4*)(W + (size_t)(k0 + row) * 64 + cg * 4);
        }
        __syncthreads();

#pragma unroll 8
        for (int k = 0; k < 32; k++) {
            float4 w = *(float4*)&sW[k][tx * 4];
            ull b0, b1, b2, b3;
            PACK2(b0, w.x, w.x);
            PACK2(b1, w.y, w.y);
            PACK2(b2, w.z, w.z);
            PACK2(b3, w.w, w.w);
            const ull* ap = (const ull*)&sAT[k][ty * 8];
            ull a0 = ap[0], a1 = ap[1], a2 = ap[2], a3 = ap[3];
            FMA2(acc[0][0], a0, b0, acc[0][0]);
            FMA2(acc[0][1], a0, b1, acc[0][1]);
            FMA2(acc[0][2], a0, b2, acc[0][2]);
            FMA2(acc[0][3], a0, b3, acc[0][3]);
            FMA2(acc[1][0], a1, b0, acc[1][0]);
            FMA2(acc[1][1], a1, b1, acc[1][1]);
            FMA2(acc[1][2], a1, b2, acc[1][2]);
            FMA2(acc[1][3], a1, b3, acc[1][3]);
            FMA2(acc[2][0], a2, b0, acc[2][0]);
            FMA2(acc[2][1], a2, b1, acc[2][1]);
            FMA2(acc[2][2], a2, b2, acc[2][2]);
            FMA2(acc[2][3], a2, b3, acc[2][3]);
            FMA2(acc[3][0], a3, b0, acc[3][0]);
            FMA2(acc[3][1], a3, b1, acc[3][1]);
            FMA2(acc[3][2], a3, b2, acc[3][2]);
            FMA2(acc[3][3], a3, b3, acc[3][3]);
        }
        __syncthreads();
    }

    int col = tx * 4;
    if (col < 40) {
        float4 bo = *(const float4*)(bias_out + col);
#pragma unroll
        for (int p = 0; p < 4; p++) {
            float4 v0, v1;
            UNPK2(v0.x, v1.x, acc[p][0]);
            UNPK2(v0.y, v1.y, acc[p][1]);
            UNPK2(v0.z, v1.z, acc[p][2]);
            UNPK2(v0.w, v1.w, acc[p][3]);
            int gr0 = r0 + ty * 8 + 2 * p;
            if (gr0 < M) {
                v0.x += bo.x; v0.y += bo.y; v0.z += bo.z; v0.w += bo.w;
                *(float4*)(C + (size_t)gr0 * 40 + col) = v0;
            }
            if (gr0 + 1 < M) {
                v1.x += bo.x; v1.y += bo.y; v1.z += bo.z; v1.w += bo.w;
                *(float4*)(C + (size_t)(gr0 + 1) * 40 + col) = v1;
            }
        }
    }
}

// ---------------------------------------------------------------------------
// prep: pad Wc, pre-round W1/W2 to tf32 (rna), seed counts with self-loop
// ---------------------------------------------------------------------------
__global__ void prep_k(const float* __restrict__ wc, float* __restrict__ wpad,
                       const float* __restrict__ w1, float* __restrict__ w1tf,
                       const float* __restrict__ w2, float* __restrict__ w2tf,
                       int* __restrict__ cnt, int N)
{
    int t = blockIdx.x * blockDim.x + threadIdx.x;
    if (t < 128 * 64) {
        int r = t >> 6, c = t & 63;
        wpad[t] = (c < 40) ? wc[r * 40 + c] : 0.f;
    }
    if (t < 128 * 128) {
        w1tf[t] = __uint_as_float(f2tf(w1[t]));
        w2tf[t] = __uint_as_float(f2tf(w2[t]));
    }
    if (t < N) cnt[t] = 1;
}

// ---------------------------------------------------------------------------
// CSR build: count, 3-kernel scan, scatter fill
// ---------------------------------------------------------------------------
__global__ void count_k(const int* __restrict__ ei, int E, int* __restrict__ cnt)
{
    int i = blockIdx.x * blockDim.x + threadIdx.x;
    if (i < E) atomicAdd(cnt + __ldg(ei + E + i), 1);
}

__global__ void blocksum_k(const int* __restrict__ cnt, int* __restrict__ bsum, int N)
{
    __shared__ int s[256];
    int i = blockIdx.x * 256 + threadIdx.x;
    s[threadIdx.x] = (i < N) ? cnt[i] : 0;
    __syncthreads();
#pragma unroll
    for (int st = 128; st > 0; st >>= 1) {
        if (threadIdx.x < st) s[threadIdx.x] += s[threadIdx.x + st];
        __syncthreads();
    }
    if (threadIdx.x == 0) bsum[blockIdx.x] = s[0];
}

__global__ void scan_bsums_k(int* __restrict__ bsum, int NB)
{
    __shared__ int s[NBMAX];
    int t = threadIdx.x;
    int x = (t < NB) ? bsum[t] : 0;
    s[t] = x;
    __syncthreads();
#pragma unroll
    for (int off = 1; off < NBMAX; off <<= 1) {
        int v = (t >= off) ? s[t - off] : 0;
        __syncthreads();
        s[t] += v;
        __syncthreads();
    }
    bsum[t < NBMAX ? t : 0] = s[t] - x;
}

__global__ void scan_final_k(const int* __restrict__ cnt,
                             const int* __restrict__ boff,
                             int* __restrict__ rowptr,
                             int* __restrict__ wcur, int N)
{
    __shared__ int s[256];
    int t = threadIdx.x;
    int i = blockIdx.x * 256 + t;
    int x = (i < N) ? cnt[i] : 0;
    s[t] = x;
    __syncthreads();
#pragma unroll
    for (int off = 1; off < 256; off <<= 1) {
        int v = (t >= off) ? s[t - off] : 0;
        __syncthreads();
        s[t] += v;
        __syncthreads();
    }
    int excl = s[t] - x + boff[blockIdx.x];
    if (i < N) {
        rowptr[i] = excl;
        wcur[i] = excl;
        if (i == N - 1) rowptr[N] = excl + x;
    }
}

__global__ void fill_k(const int* __restrict__ ei, int E, int N,
                       int* __restrict__ wcur, int* __restrict__ csrc)
{
    int t = blockIdx.x * blockDim.x + threadIdx.x;
    int T = E + N;
    if (t >= T) return;
    int s, d;
    if (t < E) { s = __ldg(ei + t); d = __ldg(ei + E + t); }
    else       { s = t - E; d = s; }
    int pos = atomicAdd(wcur + d, 1);
    csrc[pos] = s;
}

// ---------------------------------------------------------------------------
// Aggregation: warp per dst node; two half-warps, 2-deep prefetch each
// (4 edges in flight per warp). Epilogue applies relu(x + bias).
// ---------------------------------------------------------------------------
__global__ void __launch_bounds__(256) agg_k(
    const int* __restrict__ rowptr, const int* __restrict__ csrc,
    const __half* __restrict__ h16,
    const float* __restrict__ a_s, const float* __restrict__ a_d,
    const float* __restrict__ bias, float* __restrict__ out, int N)
{
    int d = (blockIdx.x * blockDim.x + threadIdx.x) >> 5;
    int lane = threadIdx.x & 31;
    if (d >= N) return;

    const int half = lane >> 4;
    const int sl = lane & 15;
    const int head = sl >> 2;
    int beg = __ldg(rowptr + d);
    int end = __ldg(rowptr + d + 1);
    float ed = __ldg(a_d + 4 * (size_t)d + head);

    float acc[8];
#pragma unroll
    for (int j = 0; j < 8; j++) acc[j] = 0.f;
    float den = 0.f;

    int eA = beg + half;
    int eB = eA + 2;
    bool vA = eA < end, vB = eB < end;
    float esA = 0.f, esB = 0.f;
    uint4 pkA = make_uint4(0, 0, 0, 0), pkB = make_uint4(0, 0, 0, 0);
    if (vA) {
        int s = __ldg(csrc + eA);
        esA = __ldg(a_s + 4 * (size_t)s + head);
        pkA = *(const uint4*)(h16 + (size_t)s * 128 + sl * 8);
    }
    if (vB) {
        int s = __ldg(csrc + eB);
        esB = __ldg(a_s + 4 * (size_t)s + head);
        pkB = *(const uint4*)(h16 + (size_t)s * 128 + sl * 8);
    }

    while (vA) {
        int eC = eA + 4;
        bool vC = eC < end;
        float esC = 0.f;
        uint4 pkC = make_uint4(0, 0, 0, 0);
        if (vC) {
            int s = __ldg(csrc + eC);
            esC = __ldg(a_s + 4 * (size_t)s + head);
            pkC = *(const uint4*)(h16 + (size_t)s * 128 + sl * 8);
        }
        float t = esA + ed;
        t = (t > 0.f) ? t : 0.2f * t;
        float p = __expf(t);
        den += p;
        const __half2* hp = (const __half2*)&pkA;
#pragma unroll
        for (int j = 0; j < 4; j++) {
            float2 f = __half22float2(hp[j]);
            acc[2 * j] = fmaf(p, f.x, acc[2 * j]);
            acc[2 * j + 1] = fmaf(p, f.y, acc[2 * j + 1]);
        }
        eA = eB; vA = vB; esA = esB; pkA = pkB;
        eB = eC; vB = vC; esB = esC; pkB = pkC;
    }

#pragma unroll
    for (int j = 0; j < 8; j++)
        acc[j] += __shfl_down_sync(0xFFFFFFFF, acc[j], 16);
    den += __shfl_down_sync(0xFFFFFFFF, den, 16);

    if (half == 0) {
        float inv = 1.0f / (den + 1e-16f);
        float4 b0 = *(const float4*)(bias + sl * 8);
        float4 b1 = *(const float4*)(bias + sl * 8 + 4);
        float4 v0 = make_float4(fmaxf(fmaf(acc[0], inv, b0.x), 0.f),
                                fmaxf(fmaf(acc[1], inv, b0.y), 0.f),
                                fmaxf(fmaf(acc[2], inv, b0.z), 0.f),
                                fmaxf(fmaf(acc[3], inv, b0.w), 0.f));
        float4 v1 = make_float4(fmaxf(fmaf(acc[4], inv, b1.x), 0.f),
                                fmaxf(fmaf(acc[5], inv, b1.y), 0.f),
                                fmaxf(fmaf(acc[6], inv, b1.z), 0.f),
                                fmaxf(fmaf(acc[7], inv, b1.w), 0.f));
        float4* o = (float4*)(out + (size_t)d * 128 + sl * 8);
        o[0] = v0;
        o[1] = v1;
    }
}

// ---------------------------------------------------------------------------
extern "C" void kernel_launch(void* const* d_in, const int* in_sizes, int n_in,
                              void* d_out, int out_size)
{
    const float* x   = (const float*)d_in[0];
    const int*   ei  = (const int*)  d_in[1];
    const float* W1  = (const float*)d_in[2];
    const float* as1 = (const float*)d_in[3];
    const float* ad1 = (const float*)d_in[4];
    const float* b1  = (const float*)d_in[5];
    const float* W2  = (const float*)d_in[6];
    const float* as2 = (const float*)d_in[7];
    const float* ad2 = (const float*)d_in[8];
    const float* b2  = (const float*)d_in[9];
    const float* Wc  = (const float*)d_in[10];
    const float* bc  = (const float*)d_in[11];
    float* out = (float*)d_out;

    const int N = in_sizes[0] / 128;
    const int E = in_sizes[1] / 2;

    __half* h16;
    float *obuf, *asb, *adb, *wpad, *w1tf, *w2tf;
    int *rowptr, *wcur, *csrc, *bsum;
    cudaGetSymbolAddress((void**)&h16,    g_h16);
    cudaGetSymbolAddress((void**)&obuf,   g_out);
    cudaGetSymbolAddress((void**)&asb,    g_asrc);
    cudaGetSymbolAddress((void**)&adb,    g_adst);
    cudaGetSymbolAddress((void**)&wpad,   g_wpad);
    cudaGetSymbolAddress((void**)&w1tf,   g_w1tf);
    cudaGetSymbolAddress((void**)&w2tf,   g_w2tf);
    cudaGetSymbolAddress((void**)&rowptr, g_rowptr);
    cudaGetSymbolAddress((void**)&wcur,   g_wcur);
    cudaGetSymbolAddress((void**)&csrc,   g_csrc);
    cudaGetSymbolAddress((void**)&bsum,   g_bsum);

    static bool attr_set = false;
    if (!attr_set) {
        cudaFuncSetAttribute(mma_gemm_k,
                             cudaFuncAttributeMaxDynamicSharedMemorySize,
                             SMEM_FLOATS * 4);
        attr_set = true;
    }

    const dim3 gMma((N + 127) / 128);
    const dim3 gCls((N + 127) / 128);
    const int  NB = (N + 255) / 256;
    const int  T = E + N;
    const int  gAgg = (N + 7) / 8;
    const int  smb = SMEM_FLOATS * 4;

    // order chosen so mma_gemm_k is the 4th launch (ncu -s lands there)
    prep_k<<<NB, 256>>>(Wc, wpad, W1, w1tf, W2, w2tf, wcur, N);        // 1
    count_k<<<(E + 255) / 256, 256>>>(ei, E, wcur);                    // 2
    blocksum_k<<<NB, 256>>>(wcur, bsum, N);                            // 3
    mma_gemm_k<<<gMma, 256, smb>>>(x, w1tf, h16, asb, adb, as1, ad1, N); // 4
    scan_bsums_k<<<1, NBMAX>>>(bsum, NB);                              // 5
    scan_final_k<<<NB, 256>>>(wcur, bsum, rowptr, wcur, N);            // 6
    fill_k<<<(T + 255) / 256, 256>>>(ei, E, N, wcur, csrc);            // 7

    agg_k<<<gAgg, 256>>>(rowptr, csrc, h16, asb, adb, b1, obuf, N);    // 8

    mma_gemm_k<<<gMma, 256, smb>>>(obuf, w2tf, h16, asb, adb, as2, ad2, N); // 9
    agg_k<<<gAgg, 256>>>(rowptr, csrc, h16, asb, adb, b2, obuf, N);    // 10

    gemm_cls_k<<<gCls, 256>>>(obuf, wpad, out, bc, N);                 // 11
}

// round 10
// speedup vs baseline: 1.0416x; 1.0416x over previous
#include <cuda_runtime.h>
#include <cuda_fp16.h>
#include <cstdint>

#define NN 100000
#define FDIM 128
#define EMAX 1700032
#define NBMAX 512

typedef unsigned long long ull;

// Scratch (device globals — allocation-free per harness rules)
__device__ __half g_h16[NN * FDIM];   // fp16 transformed features (messages)
__device__ float g_out[NN * FDIM];    // aggregated + relu(·+bias) output (fp32)
__device__ float g_asrc[NN * 4];
__device__ float g_adst[NN * 4];
__device__ float g_wpad[FDIM * 64];   // Wc zero-padded to 128x64
__device__ float g_w1tf[FDIM * FDIM]; // W1 pre-rounded to tf32 (rna)
__device__ float g_w2tf[FDIM * FDIM]; // W2 pre-rounded to tf32 (rna)
__device__ int   g_rowptr[NN + 1];
__device__ int   g_wcur[NN];
__device__ int   g_csrc[EMAX];
__device__ int   g_bsum[NBMAX];

// ---------------------------------------------------------------------------
// packed f32x2 helpers (classifier GEMM)
// ---------------------------------------------------------------------------
#define PACK2(out, lo, hi) \
    asm("mov.b64 %0, {%1, %2};" : "=l"(out) : "f"(lo), "f"(hi))
#define UNPK2(lo, hi, in) \
    asm("mov.b64 {%0, %1}, %2;" : "=f"(lo), "=f"(hi) : "l"(in))
#define FMA2(d, a, b, c) \
    asm("fma.rn.f32x2 %0, %1, %2, %3;" : "=l"(d) : "l"(a), "l"(b), "l"(c))

__device__ __forceinline__ uint32_t f2tf(float f) {
    uint32_t r;
    asm("cvt.rna.tf32.f32 %0, %1;" : "=r"(r) : "f"(f));
    return r;
}
#define MMA_TF32(c, a, b) \
    asm volatile("mma.sync.aligned.m16n8k8.row.col.f32.tf32.tf32.f32 " \
        "{%0,%1,%2,%3}, {%4,%5,%6,%7}, {%8,%9}, {%0,%1,%2,%3};" \
        : "+f"((c)[0]), "+f"((c)[1]), "+f"((c)[2]), "+f"((c)[3]) \
        : "r"((a)[0]), "r"((a)[1]), "r"((a)[2]), "r"((a)[3]), \
          "r"((b)[0]), "r"((b)[1]))

__device__ __forceinline__ uint32_t s2u(const void* p) {
    uint32_t a;
    asm("{ .reg .u64 t; cvta.to.shared.u64 t, %1; cvt.u32.u64 %0, t; }"
        : "=r"(a) : "l"(p));
    return a;
}
__device__ __forceinline__ void cpa16(uint32_t dst, const void* src, bool pred) {
    int sz = pred ? 16 : 0;   // src-size 0 -> zero-fill, no read
    asm volatile("cp.async.ca.shared.global [%0], [%1], 16, %2;"
                 :: "r"(dst), "l"(src), "r"(sz));
}
#define CPA_COMMIT() asm volatile("cp.async.commit_group;" ::: "memory")
#define CPA_WAIT(n)  asm volatile("cp.async.wait_group %0;" :: "n"(n) : "memory")

// rna-to-tf32 via bit trick: fp32 is sign-magnitude, so adding 0x1000 and
// letting the tensor core truncate the low 13 bits == cvt.rna.tf32.f32.
#define RNA13(u) ((u) + 0x1000u)

// dynamic smem layout (floats): A double-buf, W double-buf, att vectors
#define OFF_A0   0
#define OFF_A1   4608        // 128*36
#define OFF_W0   9216
#define OFF_W1   13440       // + 32*132
#define OFF_ATTS 17664
#define OFF_ATTD 17792
#define SMEM_FLOATS 17920    // 71680 bytes

// ---------------------------------------------------------------------------
// TF32 tensor GEMM, cp.async double-buffered, fused attention epilogue:
//   h16[M,128] = rna(A[M,128]) @ Wtf[128,128]   (A rounded via RNA13 at
//   fragment read; W pre-rounded in prep_k)
// BM=128, BN=128, BK=32, 256 threads (8 warps: 4M x 2N).
// ---------------------------------------------------------------------------
__global__ void __launch_bounds__(256) mma_gemm_k(
    const float* __restrict__ A, const float* __restrict__ Wtf,
    __half* __restrict__ h16,
    float* __restrict__ a_s, float* __restrict__ a_d,
    const float* __restrict__ att_s, const float* __restrict__ att_d, int M)
{
    extern __shared__ float smem[];
    const uint32_t sb = s2u(smem);
    const int tid = threadIdx.x;
    const int lane = tid & 31;
    const int w = tid >> 5;
    const int wm = (w & 3) * 32;
    const int wn = (w >> 2) * 64;
    const int r0 = blockIdx.x * 128;

    if (tid < 128) {
        smem[OFF_ATTS + tid] = att_s[tid];
        smem[OFF_ATTD + tid] = att_d[tid];
    }

    auto load_slab = [&](int kb, int buf) {
        const uint32_t aB = sb + (buf ? OFF_A1 : OFF_A0) * 4;
        const uint32_t wB = sb + (buf ? OFF_W1 : OFF_W0) * 4;
        // A: 128 rows x 8 float4; 256 threads -> 4 per thread
#pragma unroll
        for (int i = 0; i < 4; i++) {
            int idx = tid + i * 256;
            int row = idx >> 3, cg = idx & 7;
            int g = r0 + row;
            bool ok = g < M;
            cpa16(aB + (row * 36 + cg * 4) * 4,
                  A + (size_t)(ok ? g : 0) * 128 + kb * 32 + cg * 4, ok);
        }
        // W: 32 rows x 32 float4; 4 per thread
#pragma unroll
        for (int i = 0; i < 4; i++) {
            int idx = tid + i * 256;
            int k = idx >> 5, ng = idx & 31;
            cpa16(wB + (k * 132 + ng * 4) * 4,
                  Wtf + (size_t)(kb * 32 + k) * 128 + ng * 4, true);
        }
    };

    float acc[2][8][4];
#pragma unroll
    for (int tm = 0; tm < 2; tm++)
#pragma unroll
        for (int tn = 0; tn < 8; tn++)
#pragma unroll
            for (int i = 0; i < 4; i++) acc[tm][tn][i] = 0.f;

    load_slab(0, 0);
    CPA_COMMIT();

#pragma unroll
    for (int kb = 0; kb < 4; kb++) {
        const int buf = kb & 1;
        if (kb < 3) {
            load_slab(kb + 1, buf ^ 1);
            CPA_COMMIT();
            CPA_WAIT(1);
        } else {
            CPA_WAIT(0);
        }
        __syncthreads();

        const float* sA = smem + (buf ? OFF_A1 : OFF_A0);
        const float* sW = smem + (buf ? OFF_W1 : OFF_W0);

#pragma unroll
        for (int k8 = 0; k8 < 4; k8++) {
            const int kq = k8 * 8 + (lane & 3);
            const int rb = wm + (lane >> 2);
            const int nb = wn + (lane >> 2);
            uint32_t a[2][4], b[8][2];
#pragma unroll
            for (int tm = 0; tm < 2; tm++) {
                a[tm][0] = RNA13(__float_as_uint(sA[(rb + tm * 16 + 0) * 36 + kq]));
                a[tm][1] = RNA13(__float_as_uint(sA[(rb + tm * 16 + 8) * 36 + kq]));
                a[tm][2] = RNA13(__float_as_uint(sA[(rb + tm * 16 + 0) * 36 + kq + 4]));
                a[tm][3] = RNA13(__float_as_uint(sA[(rb + tm * 16 + 8) * 36 + kq + 4]));
            }
#pragma unroll
            for (int tn = 0; tn < 8; tn++) {
                b[tn][0] = __float_as_uint(sW[(kq + 0) * 132 + nb + tn * 8]);
                b[tn][1] = __float_as_uint(sW[(kq + 4) * 132 + nb + tn * 8]);
            }
#pragma unroll
            for (int tm = 0; tm < 2; tm++)
#pragma unroll
                for (int tn = 0; tn < 8; tn++)
                    MMA_TF32(acc[tm][tn], a[tm], b[tn]);
        }
        __syncthreads();
    }

    // ---- fused epilogue: fp16 store + attn logits from fp32 accs ----
    const float* satt_s = smem + OFF_ATTS;
    const float* satt_d = smem + OFF_ATTD;
    const int headA = wn >> 5;
#pragma unroll
    for (int tm = 0; tm < 2; tm++)
#pragma unroll
        for (int h2 = 0; h2 < 2; h2++) {
            int gr = r0 + wm + tm * 16 + (lane >> 2) + 8 * h2;
            if (gr < M) {
#pragma unroll
                for (int tn = 0; tn < 8; tn++) {
                    __half2 hh = __floats2half2_rn(acc[tm][tn][2 * h2],
                                                   acc[tm][tn][2 * h2 + 1]);
                    *(uint32_t*)(h16 + (size_t)gr * 128 + wn + tn * 8 +
                                 (lane & 3) * 2) = *(uint32_t*)&hh;
                }
            }
            float s0 = 0.f, d0 = 0.f, s1 = 0.f, d1 = 0.f;
#pragma unroll
            for (int tn = 0; tn < 4; tn++) {
                int col = wn + tn * 8 + (lane & 3) * 2;
                float x0 = acc[tm][tn][2 * h2], x1 = acc[tm][tn][2 * h2 + 1];
                s0 += x0 * satt_s[col] + x1 * satt_s[col + 1];
                d0 += x0 * satt_d[col] + x1 * satt_d[col + 1];
            }
#pragma unroll
            for (int tn = 4; tn < 8; tn++) {
                int col = wn + tn * 8 + (lane & 3) * 2;
                float x0 = acc[tm][tn][2 * h2], x1 = acc[tm][tn][2 * h2 + 1];
                s1 += x0 * satt_s[col] + x1 * satt_s[col + 1];
                d1 += x0 * satt_d[col] + x1 * satt_d[col + 1];
            }
#pragma unroll
            for (int off = 1; off <= 2; off <<= 1) {
                s0 += __shfl_xor_sync(0xFFFFFFFF, s0, off);
                d0 += __shfl_xor_sync(0xFFFFFFFF, d0, off);
                s1 += __shfl_xor_sync(0xFFFFFFFF, s1, off);
                d1 += __shfl_xor_sync(0xFFFFFFFF, d1, off);
            }
            if ((lane & 3) == 0 && gr < M) {
                a_s[(size_t)gr * 4 + headA] = s0;
                a_d[(size_t)gr * 4 + headA] = d0;
                a_s[(size_t)gr * 4 + headA + 1] = s1;
                a_d[(size_t)gr * 4 + headA + 1] = d1;
            }
        }
}

// ---------------------------------------------------------------------------
// Classifier GEMM (exact fp32 FFMA2): C[M,40] = A @ Wpad[128,64] + b_out
// (A already has relu+bias applied by agg)
// ---------------------------------------------------------------------------
__global__ void __launch_bounds__(256) gemm_cls_k(
    const float* __restrict__ A, const float* __restrict__ W,
    float* __restrict__ C, const float* __restrict__ bias_out, int M)
{
    __shared__ float sAT[32][130];
    __shared__ float sW[32][64];

    const int tid = threadIdx.x;
    const int tx = tid & 15;
    const int ty = tid >> 4;
    const int r0 = blockIdx.x * 128;

    ull acc[4][4];
#pragma unroll
    for (int p = 0; p < 4; p++)
#pragma unroll
        for (int c = 0; c < 4; c++) acc[p][c] = 0ull;

    for (int k0 = 0; k0 < 128; k0 += 32) {
#pragma unroll
        for (int i = 0; i < 4; i++) {
            int f = tid + i * 256;
            int row = f >> 3;
            int cg = f & 7;
            int grow = r0 + row;
            float4 v = make_float4(0.f, 0.f, 0.f, 0.f);
            if (grow < M)
                v = *(const float4*)(A + (size_t)grow * 128 + k0 + cg * 4);
            sAT[cg * 4 + 0][row] = v.x;
            sAT[cg * 4 + 1][row] = v.y;
            sAT[cg * 4 + 2][row] = v.z;
            sAT[cg * 4 + 3][row] = v.w;
        }
#pragma unroll
        for (int i = 0; i < 2; i++) {
            int f = tid + i * 256;
            int row = f >> 4;
            int cg = f & 15;
            *(float4*)&sW[row][cg * 4] =
                *(const float4*)(W + (size_t)(k0 + row) * 64 + cg * 4);
        }
        __syncthreads();

#pragma unroll 8
        for (int k = 0; k < 32; k++) {
            float4 w = *(float4*)&sW[k][tx * 4];
            ull b0, b1, b2, b3;
            PACK2(b0, w.x, w.x);
            PACK2(b1, w.y, w.y);
            PACK2(b2, w.z, w.z);
            PACK2(b3, w.w, w.w);
            const ull* ap = (const ull*)&sAT[k][ty * 8];
            ull a0 = ap[0], a1 = ap[1], a2 = ap[2], a3 = ap[3];
            FMA2(acc[0][0], a0, b0, acc[0][0]);
            FMA2(acc[0][1], a0, b1, acc[0][1]);
            FMA2(acc[0][2], a0, b2, acc[0][2]);
            FMA2(acc[0][3], a0, b3, acc[0][3]);
            FMA2(acc[1][0], a1, b0, acc[1][0]);
            FMA2(acc[1][1], a1, b1, acc[1][1]);
            FMA2(acc[1][2], a1, b2, acc[1][2]);
            FMA2(acc[1][3], a1, b3, acc[1][3]);
            FMA2(acc[2][0], a2, b0, acc[2][0]);
            FMA2(acc[2][1], a2, b1, acc[2][1]);
            FMA2(acc[2][2], a2, b2, acc[2][2]);
            FMA2(acc[2][3], a2, b3, acc[2][3]);
            FMA2(acc[3][0], a3, b0, acc[3][0]);
            FMA2(acc[3][1], a3, b1, acc[3][1]);
            FMA2(acc[3][2], a3, b2, acc[3][2]);
            FMA2(acc[3][3], a3, b3, acc[3][3]);
        }
        __syncthreads();
    }

    int col = tx * 4;
    if (col < 40) {
        float4 bo = *(const float4*)(bias_out + col);
#pragma unroll
        for (int p = 0; p < 4; p++) {
            float4 v0, v1;
            UNPK2(v0.x, v1.x, acc[p][0]);
            UNPK2(v0.y, v1.y, acc[p][1]);
            UNPK2(v0.z, v1.z, acc[p][2]);
            UNPK2(v0.w, v1.w, acc[p][3]);
            int gr0 = r0 + ty * 8 + 2 * p;
            if (gr0 < M) {
                v0.x += bo.x; v0.y += bo.y; v0.z += bo.z; v0.w += bo.w;
                *(float4*)(C + (size_t)gr0 * 40 + col) = v0;
            }
            if (gr0 + 1 < M) {
                v1.x += bo.x; v1.y += bo.y; v1.z += bo.z; v1.w += bo.w;
                *(float4*)(C + (size_t)(gr0 + 1) * 40 + col) = v1;
            }
        }
    }
}

// ---------------------------------------------------------------------------
// prep: pad Wc, pre-round W1/W2 to tf32 (rna), seed counts with self-loop
// ---------------------------------------------------------------------------
__global__ void prep_k(const float* __restrict__ wc, float* __restrict__ wpad,
                       const float* __restrict__ w1, float* __restrict__ w1tf,
                       const float* __restrict__ w2, float* __restrict__ w2tf,
                       int* __restrict__ cnt, int N)
{
    int t = blockIdx.x * blockDim.x + threadIdx.x;
    if (t < 128 * 64) {
        int r = t >> 6, c = t & 63;
        wpad[t] = (c < 40) ? wc[r * 40 + c] : 0.f;
    }
    if (t < 128 * 128) {
        w1tf[t] = __uint_as_float(f2tf(w1[t]));
        w2tf[t] = __uint_as_float(f2tf(w2[t]));
    }
    if (t < N) cnt[t] = 1;
}

// ---------------------------------------------------------------------------
// CSR build: count, 3-kernel scan, scatter fill
// ---------------------------------------------------------------------------
__global__ void count_k(const int* __restrict__ ei, int E, int* __restrict__ cnt)
{
    int i = blockIdx.x * blockDim.x + threadIdx.x;
    if (i < E) atomicAdd(cnt + __ldg(ei + E + i), 1);
}

__global__ void blocksum_k(const int* __restrict__ cnt, int* __restrict__ bsum, int N)
{
    __shared__ int s[256];
    int i = blockIdx.x * 256 + threadIdx.x;
    s[threadIdx.x] = (i < N) ? cnt[i] : 0;
    __syncthreads();
#pragma unroll
    for (int st = 128; st > 0; st >>= 1) {
        if (threadIdx.x < st) s[threadIdx.x] += s[threadIdx.x + st];
        __syncthreads();
    }
    if (threadIdx.x == 0) bsum[blockIdx.x] = s[0];
}

__global__ void scan_bsums_k(int* __restrict__ bsum, int NB)
{
    __shared__ int s[NBMAX];
    int t = threadIdx.x;
    int x = (t < NB) ? bsum[t] : 0;
    s[t] = x;
    __syncthreads();
#pragma unroll
    for (int off = 1; off < NBMAX; off <<= 1) {
        int v = (t >= off) ? s[t - off] : 0;
        __syncthreads();
        s[t] += v;
        __syncthreads();
    }
    bsum[t < NBMAX ? t : 0] = s[t] - x;
}

__global__ void scan_final_k(const int* __restrict__ cnt,
                             const int* __restrict__ boff,
                             int* __restrict__ rowptr,
                             int* __restrict__ wcur, int N)
{
    __shared__ int s[256];
    int t = threadIdx.x;
    int i = blockIdx.x * 256 + t;
    int x = (i < N) ? cnt[i] : 0;
    s[t] = x;
    __syncthreads();
#pragma unroll
    for (int off = 1; off < 256; off <<= 1) {
        int v = (t >= off) ? s[t - off] : 0;
        __syncthreads();
        s[t] += v;
        __syncthreads();
    }
    int excl = s[t] - x + boff[blockIdx.x];
    if (i < N) {
        rowptr[i] = excl;
        wcur[i] = excl;
        if (i == N - 1) rowptr[N] = excl + x;
    }
}

__global__ void fill_k(const int* __restrict__ ei, int E, int N,
                       int* __restrict__ wcur, int* __restrict__ csrc)
{
    int t = blockIdx.x * blockDim.x + threadIdx.x;
    int T = E + N;
    if (t >= T) return;
    int s, d;
    if (t < E) { s = __ldg(ei + t); d = __ldg(ei + E + t); }
    else       { s = t - E; d = s; }
    int pos = atomicAdd(wcur + d, 1);
    csrc[pos] = s;
}

// ---------------------------------------------------------------------------
// Aggregation: warp per dst node; two half-warps, 1-deep prefetch each
// (R8-proven loop). Epilogue applies relu(x*inv + bias).
// ---------------------------------------------------------------------------
__global__ void __launch_bounds__(256) agg_k(
    const int* __restrict__ rowptr, const int* __restrict__ csrc,
    const __half* __restrict__ h16,
    const float* __restrict__ a_s, const float* __restrict__ a_d,
    const float* __restrict__ bias, float* __restrict__ out, int N)
{
    int d = (blockIdx.x * blockDim.x + threadIdx.x) >> 5;
    int lane = threadIdx.x & 31;
    if (d >= N) return;

    const int half = lane >> 4;
    const int sl = lane & 15;          // cols sl*8 .. sl*8+7
    const int head = sl >> 2;
    int beg = __ldg(rowptr + d);
    int end = __ldg(rowptr + d + 1);
    float ed = __ldg(a_d + 4 * (size_t)d + head);

    float acc[8];
#pragma unroll
    for (int j = 0; j < 8; j++) acc[j] = 0.f;
    float den = 0.f;

    int e = beg + half;
    if (e < end) {
        int s = __ldg(csrc + e);
        float es = __ldg(a_s + 4 * (size_t)s + head);
        uint4 pk = *(const uint4*)(h16 + (size_t)s * 128 + sl * 8);
        for (;;) {
            int e2 = e + 2;
            bool more = e2 < end;
            float esN = 0.f;
            uint4 pkN = make_uint4(0, 0, 0, 0);
            if (more) {
                int sn = __ldg(csrc + e2);
                esN = __ldg(a_s + 4 * (size_t)sn + head);
                pkN = *(const uint4*)(h16 + (size_t)sn * 128 + sl * 8);
            }
            float t = es + ed;
            t = (t > 0.f) ? t : 0.2f * t;
            float p = __expf(t);
            den += p;
            const __half2* hp = (const __half2*)&pk;
#pragma unroll
            for (int j = 0; j < 4; j++) {
                float2 f = __half22float2(hp[j]);
                acc[2 * j] = fmaf(p, f.x, acc[2 * j]);
                acc[2 * j + 1] = fmaf(p, f.y, acc[2 * j + 1]);
            }
            if (!more) break;
            e = e2; es = esN; pk = pkN;
        }
    }

    // combine the two halves
#pragma unroll
    for (int j = 0; j < 8; j++)
        acc[j] += __shfl_down_sync(0xFFFFFFFF, acc[j], 16);
    den += __shfl_down_sync(0xFFFFFFFF, den, 16);

    if (half == 0) {
        float inv = 1.0f / (den + 1e-16f);
        float4 b0 = *(const float4*)(bias + sl * 8);
        float4 b1 = *(const float4*)(bias + sl * 8 + 4);
        float4 v0 = make_float4(fmaxf(fmaf(acc[0], inv, b0.x), 0.f),
                                fmaxf(fmaf(acc[1], inv, b0.y), 0.f),
                                fmaxf(fmaf(acc[2], inv, b0.z), 0.f),
                                fmaxf(fmaf(acc[3], inv, b0.w), 0.f));
        float4 v1 = make_float4(fmaxf(fmaf(acc[4], inv, b1.x), 0.f),
                                fmaxf(fmaf(acc[5], inv, b1.y), 0.f),
                                fmaxf(fmaf(acc[6], inv, b1.z), 0.f),
                                fmaxf(fmaf(acc[7], inv, b1.w), 0.f));
        float4* o = (float4*)(out + (size_t)d * 128 + sl * 8);
        o[0] = v0;
        o[1] = v1;
    }
}

// ---------------------------------------------------------------------------
extern "C" void kernel_launch(void* const* d_in, const int* in_sizes, int n_in,
                              void* d_out, int out_size)
{
    const float* x   = (const float*)d_in[0];
    const int*   ei  = (const int*)  d_in[1];
    const float* W1  = (const float*)d_in[2];
    const float* as1 = (const float*)d_in[3];
    const float* ad1 = (const float*)d_in[4];
    const float* b1  = (const float*)d_in[5];
    const float* W2  = (const float*)d_in[6];
    const float* as2 = (const float*)d_in[7];
    const float* ad2 = (const float*)d_in[8];
    const float* b2  = (const float*)d_in[9];
    const float* Wc  = (const float*)d_in[10];
    const float* bc  = (const float*)d_in[11];
    float* out = (float*)d_out;

    const int N = in_sizes[0] / 128;
    const int E = in_sizes[1] / 2;

    __half* h16;
    float *obuf, *asb, *adb, *wpad, *w1tf, *w2tf;
    int *rowptr, *wcur, *csrc, *bsum;
    cudaGetSymbolAddress((void**)&h16,    g_h16);
    cudaGetSymbolAddress((void**)&obuf,   g_out);
    cudaGetSymbolAddress((void**)&asb,    g_asrc);
    cudaGetSymbolAddress((void**)&adb,    g_adst);
    cudaGetSymbolAddress((void**)&wpad,   g_wpad);
    cudaGetSymbolAddress((void**)&w1tf,   g_w1tf);
    cudaGetSymbolAddress((void**)&w2tf,   g_w2tf);
    cudaGetSymbolAddress((void**)&rowptr, g_rowptr);
    cudaGetSymbolAddress((void**)&wcur,   g_wcur);
    cudaGetSymbolAddress((void**)&csrc,   g_csrc);
    cudaGetSymbolAddress((void**)&bsum,   g_bsum);

    static bool attr_set = false;
    if (!attr_set) {
        cudaFuncSetAttribute(mma_gemm_k,
                             cudaFuncAttributeMaxDynamicSharedMemorySize,
                             SMEM_FLOATS * 4);
        attr_set = true;
    }

    const dim3 gMma((N + 127) / 128);
    const dim3 gCls((N + 127) / 128);
    const int  NB = (N + 255) / 256;
    const int  T = E + N;
    const int  gAgg = (N + 7) / 8;
    const int  smb = SMEM_FLOATS * 4;

    // order chosen so mma_gemm_k is the 4th launch (ncu -s lands there)
    prep_k<<<NB, 256>>>(Wc, wpad, W1, w1tf, W2, w2tf, wcur, N);        // 1
    count_k<<<(E + 255) / 256, 256>>>(ei, E, wcur);                    // 2
    blocksum_k<<<NB, 256>>>(wcur, bsum, N);                            // 3
    mma_gemm_k<<<gMma, 256, smb>>>(x, w1tf, h16, asb, adb, as1, ad1, N); // 4
    scan_bsums_k<<<1, NBMAX>>>(bsum, NB);                              // 5
    scan_final_k<<<NB, 256>>>(wcur, bsum, rowptr, wcur, N);            // 6
    fill_k<<<(T + 255) / 256, 256>>>(ei, E, N, wcur, csrc);            // 7

    agg_k<<<gAgg, 256>>>(rowptr, csrc, h16, asb, adb, b1, obuf, N);    // 8

    mma_gemm_k<<<gMma, 256, smb>>>(obuf, w2tf, h16, asb, adb, as2, ad2, N); // 9
    agg_k<<<gAgg, 256>>>(rowptr, csrc, h16, asb, adb, b2, obuf, N);    // 10

    gemm_cls_k<<<gCls, 256>>>(obuf, wpad, out, bc, N);                 // 11
}

// round 11
// speedup vs baseline: 1.0491x; 1.0072x over previous
#include <cuda_runtime.h>
#include <cuda_fp16.h>
#include <cstdint>

#define NN 100000
#define FDIM 128
#define EMAX 1700032
#define NBMAX 512

typedef unsigned long long ull;

// Scratch (device globals — allocation-free per harness rules)
__device__ __half g_h16[NN * FDIM];   // fp16 transformed features (messages)
__device__ float g_out[NN * FDIM];    // aggregated + relu(·+bias) output (fp32)
__device__ float g_asrc[NN * 4];
__device__ float g_adst[NN * 4];
__device__ float g_wpad[FDIM * 64];   // Wc zero-padded to 128x64
__device__ float g_w1tf[FDIM * FDIM]; // W1 pre-rounded to tf32 (rna)
__device__ float g_w2tf[FDIM * FDIM]; // W2 pre-rounded to tf32 (rna)
__device__ int   g_rowptr[NN + 1];
__device__ int   g_wcur[NN];
__device__ int   g_csrc[EMAX];
__device__ int   g_bsum[NBMAX];

// ---------------------------------------------------------------------------
// packed f32x2 helpers (classifier GEMM)
// ---------------------------------------------------------------------------
#define PACK2(out, lo, hi) \
    asm("mov.b64 %0, {%1, %2};" : "=l"(out) : "f"(lo), "f"(hi))
#define UNPK2(lo, hi, in) \
    asm("mov.b64 {%0, %1}, %2;" : "=f"(lo), "=f"(hi) : "l"(in))
#define FMA2(d, a, b, c) \
    asm("fma.rn.f32x2 %0, %1, %2, %3;" : "=l"(d) : "l"(a), "l"(b), "l"(c))

__device__ __forceinline__ uint32_t f2tf(float f) {
    uint32_t r;
    asm("cvt.rna.tf32.f32 %0, %1;" : "=r"(r) : "f"(f));
    return r;
}
#define MMA_TF32(c, a, b) \
    asm volatile("mma.sync.aligned.m16n8k8.row.col.f32.tf32.tf32.f32 " \
        "{%0,%1,%2,%3}, {%4,%5,%6,%7}, {%8,%9}, {%0,%1,%2,%3};" \
        : "+f"((c)[0]), "+f"((c)[1]), "+f"((c)[2]), "+f"((c)[3]) \
        : "r"((a)[0]), "r"((a)[1]), "r"((a)[2]), "r"((a)[3]), \
          "r"((b)[0]), "r"((b)[1]))

__device__ __forceinline__ uint32_t s2u(const void* p) {
    uint32_t a;
    asm("{ .reg .u64 t; cvta.to.shared.u64 t, %1; cvt.u32.u64 %0, t; }"
        : "=r"(a) : "l"(p));
    return a;
}
__device__ __forceinline__ void cpa16(uint32_t dst, const void* src, bool pred) {
    int sz = pred ? 16 : 0;   // src-size 0 -> zero-fill, no read
    asm volatile("cp.async.ca.shared.global [%0], [%1], 16, %2;"
                 :: "r"(dst), "l"(src), "r"(sz));
}
#define CPA_COMMIT() asm volatile("cp.async.commit_group;" ::: "memory")
#define CPA_WAIT(n)  asm volatile("cp.async.wait_group %0;" :: "n"(n) : "memory")

// rna-to-tf32 via bit trick: fp32 is sign-magnitude, so adding 0x1000 and
// letting the tensor core truncate the low 13 bits == cvt.rna.tf32.f32.
#define RNA13(u) ((u) + 0x1000u)

// dynamic smem layout (floats): A double-buf, W double-buf, att vectors
#define OFF_A0   0
#define OFF_A1   4608        // 128*36
#define OFF_W0   9216
#define OFF_W1   13440       // + 32*132
#define OFF_ATTS 17664
#define OFF_ATTD 17792
#define SMEM_FLOATS 17920    // 71680 bytes

// ---------------------------------------------------------------------------
// TF32 tensor GEMM, cp.async double-buffered, fused attention epilogue.
// 512 threads, 16 warps (4M x 4N), warp tile 32x32 -> 32 acc regs/thread,
// so the CTA fits the RF as ONE 16-warp block (2x the resident warps of the
// 256-thread/134-reg version). Each warp's 32 cols = exactly one head.
//   h16[M,128] = rna(A[M,128]) @ Wtf[128,128]
// ---------------------------------------------------------------------------
__global__ void __launch_bounds__(512) mma_gemm_k(
    const float* __restrict__ A, const float* __restrict__ Wtf,
    __half* __restrict__ h16,
    float* __restrict__ a_s, float* __restrict__ a_d,
    const float* __restrict__ att_s, const float* __restrict__ att_d, int M)
{
    extern __shared__ float smem[];
    const uint32_t sb = s2u(smem);
    const int tid = threadIdx.x;
    const int lane = tid & 31;
    const int w = tid >> 5;
    const int wm = (w & 3) * 32;       // warp row base (4 M-groups)
    const int wn = (w >> 2) * 32;      // warp col base (4 N-groups = 4 heads)
    const int r0 = blockIdx.x * 128;

    if (tid < 128) {
        smem[OFF_ATTS + tid] = att_s[tid];
        smem[OFF_ATTD + tid] = att_d[tid];
    }

    auto load_slab = [&](int kb, int buf) {
        const uint32_t aB = sb + (buf ? OFF_A1 : OFF_A0) * 4;
        const uint32_t wB = sb + (buf ? OFF_W1 : OFF_W0) * 4;
        // A: 128 rows x 8 float4 = 1024; 512 threads -> 2 per thread
#pragma unroll
        for (int i = 0; i < 2; i++) {
            int idx = tid + i * 512;
            int row = idx >> 3, cg = idx & 7;
            int g = r0 + row;
            bool ok = g < M;
            cpa16(aB + (row * 36 + cg * 4) * 4,
                  A + (size_t)(ok ? g : 0) * 128 + kb * 32 + cg * 4, ok);
        }
        // W: 32 rows x 32 float4 = 1024; 2 per thread
#pragma unroll
        for (int i = 0; i < 2; i++) {
            int idx = tid + i * 512;
            int k = idx >> 5, ng = idx & 31;
            cpa16(wB + (k * 132 + ng * 4) * 4,
                  Wtf + (size_t)(kb * 32 + k) * 128 + ng * 4, true);
        }
    };

    float acc[2][4][4];
#pragma unroll
    for (int tm = 0; tm < 2; tm++)
#pragma unroll
        for (int tn = 0; tn < 4; tn++)
#pragma unroll
            for (int i = 0; i < 4; i++) acc[tm][tn][i] = 0.f;

    load_slab(0, 0);
    CPA_COMMIT();

#pragma unroll
    for (int kb = 0; kb < 4; kb++) {
        const int buf = kb & 1;
        if (kb < 3) {
            load_slab(kb + 1, buf ^ 1);
            CPA_COMMIT();
            CPA_WAIT(1);
        } else {
            CPA_WAIT(0);
        }
        __syncthreads();

        const float* sA = smem + (buf ? OFF_A1 : OFF_A0);
        const float* sW = smem + (buf ? OFF_W1 : OFF_W0);

#pragma unroll
        for (int k8 = 0; k8 < 4; k8++) {
            const int kq = k8 * 8 + (lane & 3);
            const int rb = wm + (lane >> 2);
            const int nb = wn + (lane >> 2);
            uint32_t a[2][4], b[4][2];
#pragma unroll
            for (int tm = 0; tm < 2; tm++) {
                a[tm][0] = RNA13(__float_as_uint(sA[(rb + tm * 16 + 0) * 36 + kq]));
                a[tm][1] = RNA13(__float_as_uint(sA[(rb + tm * 16 + 8) * 36 + kq]));
                a[tm][2] = RNA13(__float_as_uint(sA[(rb + tm * 16 + 0) * 36 + kq + 4]));
                a[tm][3] = RNA13(__float_as_uint(sA[(rb + tm * 16 + 8) * 36 + kq + 4]));
            }
#pragma unroll
            for (int tn = 0; tn < 4; tn++) {
                b[tn][0] = __float_as_uint(sW[(kq + 0) * 132 + nb + tn * 8]);
                b[tn][1] = __float_as_uint(sW[(kq + 4) * 132 + nb + tn * 8]);
            }
#pragma unroll
            for (int tm = 0; tm < 2; tm++)
#pragma unroll
                for (int tn = 0; tn < 4; tn++)
                    MMA_TF32(acc[tm][tn], a[tm], b[tn]);
        }
        __syncthreads();
    }

    // ---- fused epilogue: fp16 store + attn logits (one head per warp) ----
    const float* satt_s = smem + OFF_ATTS;
    const float* satt_d = smem + OFF_ATTD;
    const int head = wn >> 5;
#pragma unroll
    for (int tm = 0; tm < 2; tm++)
#pragma unroll
        for (int h2 = 0; h2 < 2; h2++) {
            int gr = r0 + wm + tm * 16 + (lane >> 2) + 8 * h2;
            if (gr < M) {
#pragma unroll
                for (int tn = 0; tn < 4; tn++) {
                    __half2 hh = __floats2half2_rn(acc[tm][tn][2 * h2],
                                                   acc[tm][tn][2 * h2 + 1]);
                    *(uint32_t*)(h16 + (size_t)gr * 128 + wn + tn * 8 +
                                 (lane & 3) * 2) = *(uint32_t*)&hh;
                }
            }
            float s0 = 0.f, d0 = 0.f;
#pragma unroll
            for (int tn = 0; tn < 4; tn++) {
                int col = wn + tn * 8 + (lane & 3) * 2;
                float x0 = acc[tm][tn][2 * h2], x1 = acc[tm][tn][2 * h2 + 1];
                s0 += x0 * satt_s[col] + x1 * satt_s[col + 1];
                d0 += x0 * satt_d[col] + x1 * satt_d[col + 1];
            }
#pragma unroll
            for (int off = 1; off <= 2; off <<= 1) {
                s0 += __shfl_xor_sync(0xFFFFFFFF, s0, off);
                d0 += __shfl_xor_sync(0xFFFFFFFF, d0, off);
            }
            if ((lane & 3) == 0 && gr < M) {
                a_s[(size_t)gr * 4 + head] = s0;
                a_d[(size_t)gr * 4 + head] = d0;
            }
        }
}

// ---------------------------------------------------------------------------
// Classifier GEMM (exact fp32 FFMA2): C[M,40] = A @ Wpad[128,64] + b_out
// (A already has relu+bias applied by agg)
// ---------------------------------------------------------------------------
__global__ void __launch_bounds__(256) gemm_cls_k(
    const float* __restrict__ A, const float* __restrict__ W,
    float* __restrict__ C, const float* __restrict__ bias_out, int M)
{
    __shared__ float sAT[32][130];
    __shared__ float sW[32][64];

    const int tid = threadIdx.x;
    const int tx = tid & 15;
    const int ty = tid >> 4;
    const int r0 = blockIdx.x * 128;

    ull acc[4][4];
#pragma unroll
    for (int p = 0; p < 4; p++)
#pragma unroll
        for (int c = 0; c < 4; c++) acc[p][c] = 0ull;

    for (int k0 = 0; k0 < 128; k0 += 32) {
#pragma unroll
        for (int i = 0; i < 4; i++) {
            int f = tid + i * 256;
            int row = f >> 3;
            int cg = f & 7;
            int grow = r0 + row;
            float4 v = make_float4(0.f, 0.f, 0.f, 0.f);
            if (grow < M)
                v = *(const float4*)(A + (size_t)grow * 128 + k0 + cg * 4);
            sAT[cg * 4 + 0][row] = v.x;
            sAT[cg * 4 + 1][row] = v.y;
            sAT[cg * 4 + 2][row] = v.z;
            sAT[cg * 4 + 3][row] = v.w;
        }
#pragma unroll
        for (int i = 0; i < 2; i++) {
            int f = tid + i * 256;
            int row = f >> 4;
            int cg = f & 15;
            *(float4*)&sW[row][cg * 4] =
                *(const float4*)(W + (size_t)(k0 + row) * 64 + cg * 4);
        }
        __syncthreads();

#pragma unroll 8
        for (int k = 0; k < 32; k++) {
            float4 w = *(float4*)&sW[k][tx * 4];
            ull b0, b1, b2, b3;
            PACK2(b0, w.x, w.x);
            PACK2(b1, w.y, w.y);
            PACK2(b2, w.z, w.z);
            PACK2(b3, w.w, w.w);
            const ull* ap = (const ull*)&sAT[k][ty * 8];
            ull a0 = ap[0], a1 = ap[1], a2 = ap[2], a3 = ap[3];
            FMA2(acc[0][0], a0, b0, acc[0][0]);
            FMA2(acc[0][1], a0, b1, acc[0][1]);
            FMA2(acc[0][2], a0, b2, acc[0][2]);
            FMA2(acc[0][3], a0, b3, acc[0][3]);
            FMA2(acc[1][0], a1, b0, acc[1][0]);
            FMA2(acc[1][1], a1, b1, acc[1][1]);
            FMA2(acc[1][2], a1, b2, acc[1][2]);
            FMA2(acc[1][3], a1, b3, acc[1][3]);
            FMA2(acc[2][0], a2, b0, acc[2][0]);
            FMA2(acc[2][1], a2, b1, acc[2][1]);
            FMA2(acc[2][2], a2, b2, acc[2][2]);
            FMA2(acc[2][3], a2, b3, acc[2][3]);
            FMA2(acc[3][0], a3, b0, acc[3][0]);
            FMA2(acc[3][1], a3, b1, acc[3][1]);
            FMA2(acc[3][2], a3, b2, acc[3][2]);
            FMA2(acc[3][3], a3, b3, acc[3][3]);
        }
        __syncthreads();
    }

    int col = tx * 4;
    if (col < 40) {
        float4 bo = *(const float4*)(bias_out + col);
#pragma unroll
        for (int p = 0; p < 4; p++) {
            float4 v0, v1;
            UNPK2(v0.x, v1.x, acc[p][0]);
            UNPK2(v0.y, v1.y, acc[p][1]);
            UNPK2(v0.z, v1.z, acc[p][2]);
            UNPK2(v0.w, v1.w, acc[p][3]);
            int gr0 = r0 + ty * 8 + 2 * p;
            if (gr0 < M) {
                v0.x += bo.x; v0.y += bo.y; v0.z += bo.z; v0.w += bo.w;
                *(float4*)(C + (size_t)gr0 * 40 + col) = v0;
            }
            if (gr0 + 1 < M) {
                v1.x += bo.x; v1.y += bo.y; v1.z += bo.z; v1.w += bo.w;
                *(float4*)(C + (size_t)(gr0 + 1) * 40 + col) = v1;
            }
        }
    }
}

// ---------------------------------------------------------------------------
// prep: pad Wc, pre-round W1/W2 to tf32 (rna), seed counts with self-loop
// ---------------------------------------------------------------------------
__global__ void prep_k(const float* __restrict__ wc, float* __restrict__ wpad,
                       const float* __restrict__ w1, float* __restrict__ w1tf,
                       const float* __restrict__ w2, float* __restrict__ w2tf,
                       int* __restrict__ cnt, int N)
{
    int t = blockIdx.x * blockDim.x + threadIdx.x;
    if (t < 128 * 64) {
        int r = t >> 6, c = t & 63;
        wpad[t] = (c < 40) ? wc[r * 40 + c] : 0.f;
    }
    if (t < 128 * 128) {
        w1tf[t] = __uint_as_float(f2tf(w1[t]));
        w2tf[t] = __uint_as_float(f2tf(w2[t]));
    }
    if (t < N) cnt[t] = 1;
}

// ---------------------------------------------------------------------------
// CSR build: count, 3-kernel scan, scatter fill
// ---------------------------------------------------------------------------
__global__ void count_k(const int* __restrict__ ei, int E, int* __restrict__ cnt)
{
    int i = blockIdx.x * blockDim.x + threadIdx.x;
    if (i < E) atomicAdd(cnt + __ldg(ei + E + i), 1);
}

__global__ void blocksum_k(const int* __restrict__ cnt, int* __restrict__ bsum, int N)
{
    __shared__ int s[256];
    int i = blockIdx.x * 256 + threadIdx.x;
    s[threadIdx.x] = (i < N) ? cnt[i] : 0;
    __syncthreads();
#pragma unroll
    for (int st = 128; st > 0; st >>= 1) {
        if (threadIdx.x < st) s[threadIdx.x] += s[threadIdx.x + st];
        __syncthreads();
    }
    if (threadIdx.x == 0) bsum[blockIdx.x] = s[0];
}

__global__ void scan_bsums_k(int* __restrict__ bsum, int NB)
{
    __shared__ int s[NBMAX];
    int t = threadIdx.x;
    int x = (t < NB) ? bsum[t] : 0;
    s[t] = x;
    __syncthreads();
#pragma unroll
    for (int off = 1; off < NBMAX; off <<= 1) {
        int v = (t >= off) ? s[t - off] : 0;
        __syncthreads();
        s[t] += v;
        __syncthreads();
    }
    bsum[t < NBMAX ? t : 0] = s[t] - x;
}

__global__ void scan_final_k(const int* __restrict__ cnt,
                             const int* __restrict__ boff,
                             int* __restrict__ rowptr,
                             int* __restrict__ wcur, int N)
{
    __shared__ int s[256];
    int t = threadIdx.x;
    int i = blockIdx.x * 256 + t;
    int x = (i < N) ? cnt[i] : 0;
    s[t] = x;
    __syncthreads();
#pragma unroll
    for (int off = 1; off < 256; off <<= 1) {
        int v = (t >= off) ? s[t - off] : 0;
        __syncthreads();
        s[t] += v;
        __syncthreads();
    }
    int excl = s[t] - x + boff[blockIdx.x];
    if (i < N) {
        rowptr[i] = excl;
        wcur[i] = excl;
        if (i == N - 1) rowptr[N] = excl + x;
    }
}

__global__ void fill_k(const int* __restrict__ ei, int E, int N,
                       int* __restrict__ wcur, int* __restrict__ csrc)
{
    int t = blockIdx.x * blockDim.x + threadIdx.x;
    int T = E + N;
    if (t >= T) return;
    int s, d;
    if (t < E) { s = __ldg(ei + t); d = __ldg(ei + E + t); }
    else       { s = t - E; d = s; }
    int pos = atomicAdd(wcur + d, 1);
    csrc[pos] = s;
}

// ---------------------------------------------------------------------------
// Aggregation: warp per dst node; two half-warps, 1-deep prefetch each
// (R8-proven loop). Epilogue applies relu(x*inv + bias).
// ---------------------------------------------------------------------------
__global__ void __launch_bounds__(256) agg_k(
    const int* __restrict__ rowptr, const int* __restrict__ csrc,
    const __half* __restrict__ h16,
    const float* __restrict__ a_s, const float* __restrict__ a_d,
    const float* __restrict__ bias, float* __restrict__ out, int N)
{
    int d = (blockIdx.x * blockDim.x + threadIdx.x) >> 5;
    int lane = threadIdx.x & 31;
    if (d >= N) return;

    const int half = lane >> 4;
    const int sl = lane & 15;          // cols sl*8 .. sl*8+7
    const int head = sl >> 2;
    int beg = __ldg(rowptr + d);
    int end = __ldg(rowptr + d + 1);
    float ed = __ldg(a_d + 4 * (size_t)d + head);

    float acc[8];
#pragma unroll
    for (int j = 0; j < 8; j++) acc[j] = 0.f;
    float den = 0.f;

    int e = beg + half;
    if (e < end) {
        int s = __ldg(csrc + e);
        float es = __ldg(a_s + 4 * (size_t)s + head);
        uint4 pk = *(const uint4*)(h16 + (size_t)s * 128 + sl * 8);
        for (;;) {
            int e2 = e + 2;
            bool more = e2 < end;
            float esN = 0.f;
            uint4 pkN = make_uint4(0, 0, 0, 0);
            if (more) {
                int sn = __ldg(csrc + e2);
                esN = __ldg(a_s + 4 * (size_t)sn + head);
                pkN = *(const uint4*)(h16 + (size_t)sn * 128 + sl * 8);
            }
            float t = es + ed;
            t = (t > 0.f) ? t : 0.2f * t;
            float p = __expf(t);
            den += p;
            const __half2* hp = (const __half2*)&pk;
#pragma unroll
            for (int j = 0; j < 4; j++) {
                float2 f = __half22float2(hp[j]);
                acc[2 * j] = fmaf(p, f.x, acc[2 * j]);
                acc[2 * j + 1] = fmaf(p, f.y, acc[2 * j + 1]);
            }
            if (!more) break;
            e = e2; es = esN; pk = pkN;
        }
    }

    // combine the two halves
#pragma unroll
    for (int j = 0; j < 8; j++)
        acc[j] += __shfl_down_sync(0xFFFFFFFF, acc[j], 16);
    den += __shfl_down_sync(0xFFFFFFFF, den, 16);

    if (half == 0) {
        float inv = 1.0f / (den + 1e-16f);
        float4 b0 = *(const float4*)(bias + sl * 8);
        float4 b1 = *(const float4*)(bias + sl * 8 + 4);
        float4 v0 = make_float4(fmaxf(fmaf(acc[0], inv, b0.x), 0.f),
                                fmaxf(fmaf(acc[1], inv, b0.y), 0.f),
                                fmaxf(fmaf(acc[2], inv, b0.z), 0.f),
                                fmaxf(fmaf(acc[3], inv, b0.w), 0.f));
        float4 v1 = make_float4(fmaxf(fmaf(acc[4], inv, b1.x), 0.f),
                                fmaxf(fmaf(acc[5], inv, b1.y), 0.f),
                                fmaxf(fmaf(acc[6], inv, b1.z), 0.f),
                                fmaxf(fmaf(acc[7], inv, b1.w), 0.f));
        float4* o = (float4*)(out + (size_t)d * 128 + sl * 8);
        o[0] = v0;
        o[1] = v1;
    }
}

// ---------------------------------------------------------------------------
extern "C" void kernel_launch(void* const* d_in, const int* in_sizes, int n_in,
                              void* d_out, int out_size)
{
    const float* x   = (const float*)d_in[0];
    const int*   ei  = (const int*)  d_in[1];
    const float* W1  = (const float*)d_in[2];
    const float* as1 = (const float*)d_in[3];
    const float* ad1 = (const float*)d_in[4];
    const float* b1  = (const float*)d_in[5];
    const float* W2  = (const float*)d_in[6];
    const float* as2 = (const float*)d_in[7];
    const float* ad2 = (const float*)d_in[8];
    const float* b2  = (const float*)d_in[9];
    const float* Wc  = (const float*)d_in[10];
    const float* bc  = (const float*)d_in[11];
    float* out = (float*)d_out;

    const int N = in_sizes[0] / 128;
    const int E = in_sizes[1] / 2;

    __half* h16;
    float *obuf, *asb, *adb, *wpad, *w1tf, *w2tf;
    int *rowptr, *wcur, *csrc, *bsum;
    cudaGetSymbolAddress((void**)&h16,    g_h16);
    cudaGetSymbolAddress((void**)&obuf,   g_out);
    cudaGetSymbolAddress((void**)&asb,    g_asrc);
    cudaGetSymbolAddress((void**)&adb,    g_adst);
    cudaGetSymbolAddress((void**)&wpad,   g_wpad);
    cudaGetSymbolAddress((void**)&w1tf,   g_w1tf);
    cudaGetSymbolAddress((void**)&w2tf,   g_w2tf);
    cudaGetSymbolAddress((void**)&rowptr, g_rowptr);
    cudaGetSymbolAddress((void**)&wcur,   g_wcur);
    cudaGetSymbolAddress((void**)&csrc,   g_csrc);
    cudaGetSymbolAddress((void**)&bsum,   g_bsum);

    static bool attr_set = false;
    if (!attr_set) {
        cudaFuncSetAttribute(mma_gemm_k,
                             cudaFuncAttributeMaxDynamicSharedMemorySize,
                             SMEM_FLOATS * 4);
        attr_set = true;
    }

    const dim3 gMma((N + 127) / 128);
    const dim3 gCls((N + 127) / 128);
    const int  NB = (N + 255) / 256;
    const int  T = E + N;
    const int  gAgg = (N + 7) / 8;
    const int  smb = SMEM_FLOATS * 4;

    // order chosen so mma_gemm_k is the 4th launch (ncu -s lands there)
    prep_k<<<NB, 256>>>(Wc, wpad, W1, w1tf, W2, w2tf, wcur, N);        // 1
    count_k<<<(E + 255) / 256, 256>>>(ei, E, wcur);                    // 2
    blocksum_k<<<NB, 256>>>(wcur, bsum, N);                            // 3
    mma_gemm_k<<<gMma, 512, smb>>>(x, w1tf, h16, asb, adb, as1, ad1, N); // 4
    scan_bsums_k<<<1, NBMAX>>>(bsum, NB);                              // 5
    scan_final_k<<<NB, 256>>>(wcur, bsum, rowptr, wcur, N);            // 6
    fill_k<<<(T + 255) / 256, 256>>>(ei, E, N, wcur, csrc);            // 7

    agg_k<<<gAgg, 256>>>(rowptr, csrc, h16, asb, adb, b1, obuf, N);    // 8

    mma_gemm_k<<<gMma, 512, smb>>>(obuf, w2tf, h16, asb, adb, as2, ad2, N); // 9
    agg_k<<<gAgg, 256>>>(rowptr, csrc, h16, asb, adb, b2, obuf, N);    // 10

    gemm_cls_k<<<gCls, 256>>>(obuf, wpad, out, bc, N);                 // 11
}

// round 12
// speedup vs baseline: 1.1347x; 1.0817x over previous
#include <cuda_runtime.h>
#include <cuda_fp16.h>
#include <cstdint>

#define NN 100000
#define FDIM 128
#define EMAX 1700032
#define NBMAX 512

typedef unsigned long long ull;

// Scratch (device globals — allocation-free per harness rules)
__device__ __half g_h16[NN * FDIM];   // fp16 transformed features (messages)
__device__ float g_out[NN * FDIM];    // aggregated + relu(·+bias) output (fp32)
__device__ float g_asrc[NN * 4];
__device__ float g_adst[NN * 4];
__device__ float g_wpad[FDIM * 64];   // Wc zero-padded to 128x64
__device__ float g_w1tf[FDIM * FDIM]; // W1^T, tf32-rounded, k pair-interleaved
__device__ float g_w2tf[FDIM * FDIM]; // W2^T, tf32-rounded, k pair-interleaved
__device__ int   g_rowptr[NN + 1];
__device__ int   g_wcur[NN];
__device__ int   g_csrc[EMAX];
__device__ int   g_bsum[NBMAX];

// ---------------------------------------------------------------------------
// packed f32x2 helpers (classifier GEMM)
// ---------------------------------------------------------------------------
#define PACK2(out, lo, hi) \
    asm("mov.b64 %0, {%1, %2};" : "=l"(out) : "f"(lo), "f"(hi))
#define UNPK2(lo, hi, in) \
    asm("mov.b64 {%0, %1}, %2;" : "=f"(lo), "=f"(hi) : "l"(in))
#define FMA2(d, a, b, c) \
    asm("fma.rn.f32x2 %0, %1, %2, %3;" : "=l"(d) : "l"(a), "l"(b), "l"(c))

__device__ __forceinline__ uint32_t f2tf(float f) {
    uint32_t r;
    asm("cvt.rna.tf32.f32 %0, %1;" : "=r"(r) : "f"(f));
    return r;
}
#define MMA_TF32(c, a, b) \
    asm volatile("mma.sync.aligned.m16n8k8.row.col.f32.tf32.tf32.f32 " \
        "{%0,%1,%2,%3}, {%4,%5,%6,%7}, {%8,%9}, {%0,%1,%2,%3};" \
        : "+f"((c)[0]), "+f"((c)[1]), "+f"((c)[2]), "+f"((c)[3]) \
        : "r"((a)[0]), "r"((a)[1]), "r"((a)[2]), "r"((a)[3]), \
          "r"((b)[0]), "r"((b)[1]))

__device__ __forceinline__ uint32_t s2u(const void* p) {
    uint32_t a;
    asm("{ .reg .u64 t; cvta.to.shared.u64 t, %1; cvt.u32.u64 %0, t; }"
        : "=r"(a) : "l"(p));
    return a;
}
__device__ __forceinline__ void cpa16(uint32_t dst, const void* src, bool pred) {
    int sz = pred ? 16 : 0;   // src-size 0 -> zero-fill, no read
    asm volatile("cp.async.ca.shared.global [%0], [%1], 16, %2;"
                 :: "r"(dst), "l"(src), "r"(sz));
}
#define CPA_COMMIT() asm volatile("cp.async.commit_group;" ::: "memory")
#define CPA_WAIT(n)  asm volatile("cp.async.wait_group %0;" :: "n"(n) : "memory")

// rna-to-tf32 via bit trick: fp32 is sign-magnitude, so adding 0x1000 and
// letting the tensor core truncate the low 13 bits == cvt.rna.tf32.f32.
#define RNA13(u) ((u) + 0x1000u)

// dynamic smem layout (floats): A double-buf (stride 36), W double-buf
// ([n][k-slab] layout, stride 40), att vectors
#define OFF_A0   0
#define OFF_A1   4608        // 128*36
#define OFF_W0   9216
#define OFF_W1   14336       // + 128*40
#define OFF_ATTS 19456
#define OFF_ATTD 19584
#define SMEM_FLOATS 19712    // 78848 bytes

// ---------------------------------------------------------------------------
// TF32 tensor GEMM, cp.async double-buffered, fused attention epilogue.
// 512 threads, 16 warps (4M x 4N), warp tile 32x32.
// W fed transposed + k-pair-interleaved, so each thread's (kq, kq+4) B pair
// is one LDS.64 (per-k8 LDS: 16 -> 12). Stride 40 = conflict-free 64-bit.
//   h16[M,128] = rna(A[M,128]) @ W[128,128]
// ---------------------------------------------------------------------------
__global__ void __launch_bounds__(512) mma_gemm_k(
    const float* __restrict__ A, const float* __restrict__ WtfT,
    __half* __restrict__ h16,
    float* __restrict__ a_s, float* __restrict__ a_d,
    const float* __restrict__ att_s, const float* __restrict__ att_d, int M)
{
    extern __shared__ float smem[];
    const uint32_t sb = s2u(smem);
    const int tid = threadIdx.x;
    const int lane = tid & 31;
    const int w = tid >> 5;
    const int wm = (w & 3) * 32;       // warp row base
    const int wn = (w >> 2) * 32;      // warp col base (one head per warp)
    const int r0 = blockIdx.x * 128;

    if (tid < 128) {
        smem[OFF_ATTS + tid] = att_s[tid];
        smem[OFF_ATTD + tid] = att_d[tid];
    }

    auto load_slab = [&](int kb, int buf) {
        const uint32_t aB = sb + (buf ? OFF_A1 : OFF_A0) * 4;
        const uint32_t wB = sb + (buf ? OFF_W1 : OFF_W0) * 4;
        // A: 128 rows x 8 float4 = 1024; 2 per thread
#pragma unroll
        for (int i = 0; i < 2; i++) {
            int idx = tid + i * 512;
            int row = idx >> 3, cg = idx & 7;
            int g = r0 + row;
            bool ok = g < M;
            cpa16(aB + (row * 36 + cg * 4) * 4,
                  A + (size_t)(ok ? g : 0) * 128 + kb * 32 + cg * 4, ok);
        }
        // W^T: 128 n-rows x 8 float4 (32 permuted-k cols) = 1024; 2 per thread
#pragma unroll
        for (int i = 0; i < 2; i++) {
            int idx = tid + i * 512;
            int n = idx >> 3, cg = idx & 7;
            cpa16(wB + (n * 40 + cg * 4) * 4,
                  WtfT + (size_t)n * 128 + kb * 32 + cg * 4, true);
        }
    };

    float acc[2][4][4];
#pragma unroll
    for (int tm = 0; tm < 2; tm++)
#pragma unroll
        for (int tn = 0; tn < 4; tn++)
#pragma unroll
            for (int i = 0; i < 4; i++) acc[tm][tn][i] = 0.f;

    load_slab(0, 0);
    CPA_COMMIT();

#pragma unroll
    for (int kb = 0; kb < 4; kb++) {
        const int buf = kb & 1;
        if (kb < 3) {
            load_slab(kb + 1, buf ^ 1);
            CPA_COMMIT();
            CPA_WAIT(1);
        } else {
            CPA_WAIT(0);
        }
        __syncthreads();

        const float* sA = smem + (buf ? OFF_A1 : OFF_A0);
        const float* sW = smem + (buf ? OFF_W1 : OFF_W0);

#pragma unroll
        for (int k8 = 0; k8 < 4; k8++) {
            const int kq = k8 * 8 + (lane & 3);
            const int rb = wm + (lane >> 2);
            const int nb = wn + (lane >> 2);
            uint32_t a[2][4], b[4][2];
#pragma unroll
            for (int tm = 0; tm < 2; tm++) {
                a[tm][0] = RNA13(__float_as_uint(sA[(rb + tm * 16 + 0) * 36 + kq]));
                a[tm][1] = RNA13(__float_as_uint(sA[(rb + tm * 16 + 8) * 36 + kq]));
                a[tm][2] = RNA13(__float_as_uint(sA[(rb + tm * 16 + 0) * 36 + kq + 4]));
                a[tm][3] = RNA13(__float_as_uint(sA[(rb + tm * 16 + 8) * 36 + kq + 4]));
            }
#pragma unroll
            for (int tn = 0; tn < 4; tn++) {
                float2 bp = *(const float2*)&sW[(nb + tn * 8) * 40 +
                                                k8 * 8 + 2 * (lane & 3)];
                b[tn][0] = __float_as_uint(bp.x);   // k = kq
                b[tn][1] = __float_as_uint(bp.y);   // k = kq + 4
            }
#pragma unroll
            for (int tm = 0; tm < 2; tm++)
#pragma unroll
                for (int tn = 0; tn < 4; tn++)
                    MMA_TF32(acc[tm][tn], a[tm], b[tn]);
        }
        __syncthreads();
    }

    // ---- fused epilogue: fp16 store + attn logits (one head per warp) ----
    const float* satt_s = smem + OFF_ATTS;
    const float* satt_d = smem + OFF_ATTD;
    const int head = wn >> 5;
#pragma unroll
    for (int tm = 0; tm < 2; tm++)
#pragma unroll
        for (int h2 = 0; h2 < 2; h2++) {
            int gr = r0 + wm + tm * 16 + (lane >> 2) + 8 * h2;
            if (gr < M) {
#pragma unroll
                for (int tn = 0; tn < 4; tn++) {
                    __half2 hh = __floats2half2_rn(acc[tm][tn][2 * h2],
                                                   acc[tm][tn][2 * h2 + 1]);
                    *(uint32_t*)(h16 + (size_t)gr * 128 + wn + tn * 8 +
                                 (lane & 3) * 2) = *(uint32_t*)&hh;
                }
            }
            float s0 = 0.f, d0 = 0.f;
#pragma unroll
            for (int tn = 0; tn < 4; tn++) {
                int col = wn + tn * 8 + (lane & 3) * 2;
                float x0 = acc[tm][tn][2 * h2], x1 = acc[tm][tn][2 * h2 + 1];
                s0 += x0 * satt_s[col] + x1 * satt_s[col + 1];
                d0 += x0 * satt_d[col] + x1 * satt_d[col + 1];
            }
#pragma unroll
            for (int off = 1; off <= 2; off <<= 1) {
                s0 += __shfl_xor_sync(0xFFFFFFFF, s0, off);
                d0 += __shfl_xor_sync(0xFFFFFFFF, d0, off);
            }
            if ((lane & 3) == 0 && gr < M) {
                a_s[(size_t)gr * 4 + head] = s0;
                a_d[(size_t)gr * 4 + head] = d0;
            }
        }
}

// ---------------------------------------------------------------------------
// Classifier GEMM (exact fp32 FFMA2): C[M,40] = A @ Wpad[128,64] + b_out
// ---------------------------------------------------------------------------
__global__ void __launch_bounds__(256) gemm_cls_k(
    const float* __restrict__ A, const float* __restrict__ W,
    float* __restrict__ C, const float* __restrict__ bias_out, int M)
{
    __shared__ float sAT[32][130];
    __shared__ float sW[32][64];

    const int tid = threadIdx.x;
    const int tx = tid & 15;
    const int ty = tid >> 4;
    const int r0 = blockIdx.x * 128;

    ull acc[4][4];
#pragma unroll
    for (int p = 0; p < 4; p++)
#pragma unroll
        for (int c = 0; c < 4; c++) acc[p][c] = 0ull;

    for (int k0 = 0; k0 < 128; k0 += 32) {
#pragma unroll
        for (int i = 0; i < 4; i++) {
            int f = tid + i * 256;
            int row = f >> 3;
            int cg = f & 7;
            int grow = r0 + row;
            float4 v = make_float4(0.f, 0.f, 0.f, 0.f);
            if (grow < M)
                v = *(const float4*)(A + (size_t)grow * 128 + k0 + cg * 4);
            sAT[cg * 4 + 0][row] = v.x;
            sAT[cg * 4 + 1][row] = v.y;
            sAT[cg * 4 + 2][row] = v.z;
            sAT[cg * 4 + 3][row] = v.w;
        }
#pragma unroll
        for (int i = 0; i < 2; i++) {
            int f = tid + i * 256;
            int row = f >> 4;
            int cg = f & 15;
            *(float4*)&sW[row][cg * 4] =
                *(const float4*)(W + (size_t)(k0 + row) * 64 + cg * 4);
        }
        __syncthreads();

#pragma unroll 8
        for (int k = 0; k < 32; k++) {
            float4 w = *(float4*)&sW[k][tx * 4];
            ull b0, b1, b2, b3;
            PACK2(b0, w.x, w.x);
            PACK2(b1, w.y, w.y);
            PACK2(b2, w.z, w.z);
            PACK2(b3, w.w, w.w);
            const ull* ap = (const ull*)&sAT[k][ty * 8];
            ull a0 = ap[0], a1 = ap[1], a2 = ap[2], a3 = ap[3];
            FMA2(acc[0][0], a0, b0, acc[0][0]);
            FMA2(acc[0][1], a0, b1, acc[0][1]);
            FMA2(acc[0][2], a0, b2, acc[0][2]);
            FMA2(acc[0][3], a0, b3, acc[0][3]);
            FMA2(acc[1][0], a1, b0, acc[1][0]);
            FMA2(acc[1][1], a1, b1, acc[1][1]);
            FMA2(acc[1][2], a1, b2, acc[1][2]);
            FMA2(acc[1][3], a1, b3, acc[1][3]);
            FMA2(acc[2][0], a2, b0, acc[2][0]);
            FMA2(acc[2][1], a2, b1, acc[2][1]);
            FMA2(acc[2][2], a2, b2, acc[2][2]);
            FMA2(acc[2][3], a2, b3, acc[2][3]);
            FMA2(acc[3][0], a3, b0, acc[3][0]);
            FMA2(acc[3][1], a3, b1, acc[3][1]);
            FMA2(acc[3][2], a3, b2, acc[3][2]);
            FMA2(acc[3][3], a3, b3, acc[3][3]);
        }
        __syncthreads();
    }

    int col = tx * 4;
    if (col < 40) {
        float4 bo = *(const float4*)(bias_out + col);
#pragma unroll
        for (int p = 0; p < 4; p++) {
            float4 v0, v1;
            UNPK2(v0.x, v1.x, acc[p][0]);
            UNPK2(v0.y, v1.y, acc[p][1]);
            UNPK2(v0.z, v1.z, acc[p][2]);
            UNPK2(v0.w, v1.w, acc[p][3]);
            int gr0 = r0 + ty * 8 + 2 * p;
            if (gr0 < M) {
                v0.x += bo.x; v0.y += bo.y; v0.z += bo.z; v0.w += bo.w;
                *(float4*)(C + (size_t)gr0 * 40 + col) = v0;
            }
            if (gr0 + 1 < M) {
                v1.x += bo.x; v1.y += bo.y; v1.z += bo.z; v1.w += bo.w;
                *(float4*)(C + (size_t)(gr0 + 1) * 40 + col) = v1;
            }
        }
    }
}

// ---------------------------------------------------------------------------
// prep: pad Wc, build W1^T/W2^T tf32-rounded with k pair-interleaved
// (j-order per k8 group: 0,4,1,5,2,6,3,7), seed counts with self-loop
// ---------------------------------------------------------------------------
__global__ void prep_k(const float* __restrict__ wc, float* __restrict__ wpad,
                       const float* __restrict__ w1, float* __restrict__ w1tf,
                       const float* __restrict__ w2, float* __restrict__ w2tf,
                       int* __restrict__ cnt, int N)
{
    int t = blockIdx.x * blockDim.x + threadIdx.x;
    if (t < 128 * 64) {
        int r = t >> 6, c = t & 63;
        wpad[t] = (c < 40) ? wc[r * 40 + c] : 0.f;
    }
    if (t < 128 * 128) {
        int n = t >> 7, j = t & 127;
        int k = ((j >> 3) << 3) + ((j >> 1) & 3) + ((j & 1) << 2);
        w1tf[t] = __uint_as_float(f2tf(w1[k * 128 + n]));
        w2tf[t] = __uint_as_float(f2tf(w2[k * 128 + n]));
    }
    if (t < N) cnt[t] = 1;
}

// ---------------------------------------------------------------------------
// CSR build: count, 3-kernel scan, scatter fill
// ---------------------------------------------------------------------------
__global__ void count_k(const int* __restrict__ ei, int E, int* __restrict__ cnt)
{
    int i = blockIdx.x * blockDim.x + threadIdx.x;
    if (i < E) atomicAdd(cnt + __ldg(ei + E + i), 1);
}

__global__ void blocksum_k(const int* __restrict__ cnt, int* __restrict__ bsum, int N)
{
    __shared__ int s[256];
    int i = blockIdx.x * 256 + threadIdx.x;
    s[threadIdx.x] = (i < N) ? cnt[i] : 0;
    __syncthreads();
#pragma unroll
    for (int st = 128; st > 0; st >>= 1) {
        if (threadIdx.x < st) s[threadIdx.x] += s[threadIdx.x + st];
        __syncthreads();
    }
    if (threadIdx.x == 0) bsum[blockIdx.x] = s[0];
}

__global__ void scan_bsums_k(int* __restrict__ bsum, int NB)
{
    __shared__ int s[NBMAX];
    int t = threadIdx.x;
    int x = (t < NB) ? bsum[t] : 0;
    s[t] = x;
    __syncthreads();
#pragma unroll
    for (int off = 1; off < NBMAX; off <<= 1) {
        int v = (t >= off) ? s[t - off] : 0;
        __syncthreads();
        s[t] += v;
        __syncthreads();
    }
    bsum[t < NBMAX ? t : 0] = s[t] - x;
}

__global__ void scan_final_k(const int* __restrict__ cnt,
                             const int* __restrict__ boff,
                             int* __restrict__ rowptr,
                             int* __restrict__ wcur, int N)
{
    __shared__ int s[256];
    int t = threadIdx.x;
    int i = blockIdx.x * 256 + t;
    int x = (i < N) ? cnt[i] : 0;
    s[t] = x;
    __syncthreads();
#pragma unroll
    for (int off = 1; off < 256; off <<= 1) {
        int v = (t >= off) ? s[t - off] : 0;
        __syncthreads();
        s[t] += v;
        __syncthreads();
    }
    int excl = s[t] - x + boff[blockIdx.x];
    if (i < N) {
        rowptr[i] = excl;
        wcur[i] = excl;
        if (i == N - 1) rowptr[N] = excl + x;
    }
}

__global__ void fill_k(const int* __restrict__ ei, int E, int N,
                       int* __restrict__ wcur, int* __restrict__ csrc)
{
    int t = blockIdx.x * blockDim.x + threadIdx.x;
    int T = E + N;
    if (t >= T) return;
    int s, d;
    if (t < E) { s = __ldg(ei + t); d = __ldg(ei + E + t); }
    else       { s = t - E; d = s; }
    int pos = atomicAdd(wcur + d, 1);
    csrc[pos] = s;
}

// ---------------------------------------------------------------------------
// Aggregation: warp per dst node; two half-warps, 1-deep prefetch each.
// Epilogue applies relu(x*inv + bias).
// ---------------------------------------------------------------------------
__global__ void __launch_bounds__(256) agg_k(
    const int* __restrict__ rowptr, const int* __restrict__ csrc,
    const __half* __restrict__ h16,
    const float* __restrict__ a_s, const float* __restrict__ a_d,
    const float* __restrict__ bias, float* __restrict__ out, int N)
{
    int d = (blockIdx.x * blockDim.x + threadIdx.x) >> 5;
    int lane = threadIdx.x & 31;
    if (d >= N) return;

    const int half = lane >> 4;
    const int sl = lane & 15;          // cols sl*8 .. sl*8+7
    const int head = sl >> 2;
    int beg = __ldg(rowptr + d);
    int end = __ldg(rowptr + d + 1);
    float ed = __ldg(a_d + 4 * (size_t)d + head);

    float acc[8];
#pragma unroll
    for (int j = 0; j < 8; j++) acc[j] = 0.f;
    float den = 0.f;

    int e = beg + half;
    if (e < end) {
        int s = __ldg(csrc + e);
        float es = __ldg(a_s + 4 * (size_t)s + head);
        uint4 pk = *(const uint4*)(h16 + (size_t)s * 128 + sl * 8);
        for (;;) {
            int e2 = e + 2;
            bool more = e2 < end;
            float esN = 0.f;
            uint4 pkN = make_uint4(0, 0, 0, 0);
            if (more) {
                int sn = __ldg(csrc + e2);
                esN = __ldg(a_s + 4 * (size_t)sn + head);
                pkN = *(const uint4*)(h16 + (size_t)sn * 128 + sl * 8);
            }
            float t = es + ed;
            t = (t > 0.f) ? t : 0.2f * t;
            float p = __expf(t);
            den += p;
            const __half2* hp = (const __half2*)&pk;
#pragma unroll
            for (int j = 0; j < 4; j++) {
                float2 f = __half22float2(hp[j]);
                acc[2 * j] = fmaf(p, f.x, acc[2 * j]);
                acc[2 * j + 1] = fmaf(p, f.y, acc[2 * j + 1]);
            }
            if (!more) break;
            e = e2; es = esN; pk = pkN;
        }
    }

    // combine the two halves
#pragma unroll
    for (int j = 0; j < 8; j++)
        acc[j] += __shfl_down_sync(0xFFFFFFFF, acc[j], 16);
    den += __shfl_down_sync(0xFFFFFFFF, den, 16);

    if (half == 0) {
        float inv = 1.0f / (den + 1e-16f);
        float4 b0 = *(const float4*)(bias + sl * 8);
        float4 b1 = *(const float4*)(bias + sl * 8 + 4);
        float4 v0 = make_float4(fmaxf(fmaf(acc[0], inv, b0.x), 0.f),
                                fmaxf(fmaf(acc[1], inv, b0.y), 0.f),
                                fmaxf(fmaf(acc[2], inv, b0.z), 0.f),
                                fmaxf(fmaf(acc[3], inv, b0.w), 0.f));
        float4 v1 = make_float4(fmaxf(fmaf(acc[4], inv, b1.x), 0.f),
                                fmaxf(fmaf(acc[5], inv, b1.y), 0.f),
                                fmaxf(fmaf(acc[6], inv, b1.z), 0.f),
                                fmaxf(fmaf(acc[7], inv, b1.w), 0.f));
        float4* o = (float4*)(out + (size_t)d * 128 + sl * 8);
        o[0] = v0;
        o[1] = v1;
    }
}

// ---------------------------------------------------------------------------
extern "C" void kernel_launch(void* const* d_in, const int* in_sizes, int n_in,
                              void* d_out, int out_size)
{
    const float* x   = (const float*)d_in[0];
    const int*   ei  = (const int*)  d_in[1];
    const float* W1  = (const float*)d_in[2];
    const float* as1 = (const float*)d_in[3];
    const float* ad1 = (const float*)d_in[4];
    const float* b1  = (const float*)d_in[5];
    const float* W2  = (const float*)d_in[6];
    const float* as2 = (const float*)d_in[7];
    const float* ad2 = (const float*)d_in[8];
    const float* b2  = (const float*)d_in[9];
    const float* Wc  = (const float*)d_in[10];
    const float* bc  = (const float*)d_in[11];
    float* out = (float*)d_out;

    const int N = in_sizes[0] / 128;
    const int E = in_sizes[1] / 2;

    __half* h16;
    float *obuf, *asb, *adb, *wpad, *w1tf, *w2tf;
    int *rowptr, *wcur, *csrc, *bsum;
    cudaGetSymbolAddress((void**)&h16,    g_h16);
    cudaGetSymbolAddress((void**)&obuf,   g_out);
    cudaGetSymbolAddress((void**)&asb,    g_asrc);
    cudaGetSymbolAddress((void**)&adb,    g_adst);
    cudaGetSymbolAddress((void**)&wpad,   g_wpad);
    cudaGetSymbolAddress((void**)&w1tf,   g_w1tf);
    cudaGetSymbolAddress((void**)&w2tf,   g_w2tf);
    cudaGetSymbolAddress((void**)&rowptr, g_rowptr);
    cudaGetSymbolAddress((void**)&wcur,   g_wcur);
    cudaGetSymbolAddress((void**)&csrc,   g_csrc);
    cudaGetSymbolAddress((void**)&bsum,   g_bsum);

    // one-time host-side init (no device allocations)
    static cudaStream_t s2 = nullptr;
    static cudaEvent_t evF = nullptr, evJ = nullptr;
    if (!s2) {
        cudaStreamCreateWithFlags(&s2, cudaStreamNonBlocking);
        cudaEventCreateWithFlags(&evF, cudaEventDisableTiming);
        cudaEventCreateWithFlags(&evJ, cudaEventDisableTiming);
        cudaFuncSetAttribute(mma_gemm_k,
                             cudaFuncAttributeMaxDynamicSharedMemorySize,
                             SMEM_FLOATS * 4);
    }

    const dim3 gMma((N + 127) / 128);
    const dim3 gCls((N + 127) / 128);
    const int  NB = (N + 255) / 256;
    const int  T = E + N;
    const int  gAgg = (N + 7) / 8;
    const int  smb = SMEM_FLOATS * 4;

    // prep on main stream; CSR chain forked onto s2, overlapping GEMM-1.
    prep_k<<<NB, 256>>>(Wc, wpad, W1, w1tf, W2, w2tf, wcur, N);          // 1
    cudaEventRecord(evF, 0);
    cudaStreamWaitEvent(s2, evF, 0);

    count_k<<<(E + 255) / 256, 256, 0, s2>>>(ei, E, wcur);               // 2 (s2)
    blocksum_k<<<NB, 256, 0, s2>>>(wcur, bsum, N);                       // 3 (s2)
    mma_gemm_k<<<gMma, 512, smb>>>(x, w1tf, h16, asb, adb, as1, ad1, N); // 4 (main)
    scan_bsums_k<<<1, NBMAX, 0, s2>>>(bsum, NB);                         // 5 (s2)
    scan_final_k<<<NB, 256, 0, s2>>>(wcur, bsum, rowptr, wcur, N);       // 6 (s2)
    fill_k<<<(T + 255) / 256, 256, 0, s2>>>(ei, E, N, wcur, csrc);       // 7 (s2)
    cudaEventRecord(evJ, s2);
    cudaStreamWaitEvent(0, evJ, 0);

    agg_k<<<gAgg, 256>>>(rowptr, csrc, h16, asb, adb, b1, obuf, N);      // 8

    mma_gemm_k<<<gMma, 512, smb>>>(obuf, w2tf, h16, asb, adb, as2, ad2, N); // 9
    agg_k<<<gAgg, 256>>>(rowptr, csrc, h16, asb, adb, b2, obuf, N);      // 10

    gemm_cls_k<<<gCls, 256>>>(obuf, wpad, out, bc, N);                   // 11
}